// round 4
// baseline (speedup 1.0000x reference)
#include <cuda_runtime.h>

#define HWN   4096
#define CDIM  256
#define KCODES 1024
#define BATCH 16

// Device-global scratch (no allocations allowed in kernel_launch)
__device__ float g_ct[CDIM * KCODES];   // codebook transposed [c][k], 1 MB
__device__ float g_c2[KCODES];          // ||codebook_k||^2
__device__ int   g_inds[BATCH * HWN];   // argmin indices
__device__ float g_loss;                // loss accumulator

// ---------------------------------------------------------------------------
// Prep 1: tiled transpose codebook[k][c] -> g_ct[c][k]; also zero g_loss.
// ---------------------------------------------------------------------------
__global__ void prep_transpose(const float* __restrict__ cb) {
    __shared__ float tile[32][33];
    int k0 = blockIdx.x * 32;
    int c0 = blockIdx.y * 32;
    int tx = threadIdx.x & 31;
    int r0 = threadIdx.x >> 5;  // 0..7
#pragma unroll
    for (int i = 0; i < 4; i++) {
        int k = r0 + i * 8;
        tile[k][tx] = cb[(size_t)(k0 + k) * CDIM + c0 + tx];
    }
    __syncthreads();
#pragma unroll
    for (int i = 0; i < 4; i++) {
        int c = r0 + i * 8;
        g_ct[(size_t)(c0 + c) * KCODES + k0 + tx] = tile[tx][c];
    }
    if (blockIdx.x == 0 && blockIdx.y == 0 && threadIdx.x == 0) g_loss = 0.0f;
}

// ---------------------------------------------------------------------------
// Prep 2: c2[k] = sum_c codebook[k][c]^2   (one warp per code row)
// ---------------------------------------------------------------------------
__global__ void prep_c2(const float* __restrict__ cb) {
    int k = blockIdx.x;
    int lane = threadIdx.x;
    float s = 0.0f;
#pragma unroll
    for (int c = lane; c < CDIM; c += 32) {
        float v = cb[(size_t)k * CDIM + c];
        s += v * v;
    }
#pragma unroll
    for (int o = 16; o; o >>= 1) s += __shfl_xor_sync(0xffffffffu, s, o);
    if (lane == 0) g_c2[k] = s;
}

// ---------------------------------------------------------------------------
// SGEMM + argmin.
// Block: 256 threads, computes 64 pixels x all 1024 codes.
// Tiles: TM=64 px, TN=64 codes, TK=32 channels. 4x4 register microtile.
// d2[k] = c2[k] - 2*dot(x_n, c_k)  (||x||^2 constant per row, irrelevant
// for argmin; loss computed later from actual (q-x)^2)
// ---------------------------------------------------------------------------
__global__ __launch_bounds__(256) void gemm_argmin(const float* __restrict__ x) {
    __shared__ float As[32][64];
    __shared__ float Bs[32][64];
    __shared__ float rv[64][17];
    __shared__ int   ri[64][17];

    const int b  = blockIdx.y;
    const int n0 = blockIdx.x * 64;
    const int tid = threadIdx.x;
    const int tx = tid & 15;        // code dim (4 codes each)
    const int ty = tid >> 4;        // pixel dim (4 px each)
    const int lcol = tid & 63;      // loader column
    const int lrow = tid >> 6;      // loader row base (0..3)

    const float* xb = x + (size_t)b * CDIM * HWN + n0;

    float best[4];
    int   besti[4];
#pragma unroll
    for (int i = 0; i < 4; i++) { best[i] = 3.4e38f; besti[i] = 0; }

    for (int kt = 0; kt < KCODES / 64; kt++) {
        float acc[4][4];
#pragma unroll
        for (int i = 0; i < 4; i++)
#pragma unroll
            for (int j = 0; j < 4; j++) acc[i][j] = 0.0f;

#pragma unroll 1
        for (int cc = 0; cc < CDIM; cc += 32) {
#pragma unroll
            for (int i = 0; i < 8; i++) {
                int r = lrow + i * 4;
                As[r][lcol] = xb[(size_t)(cc + r) * HWN + lcol];
                Bs[r][lcol] = g_ct[(size_t)(cc + r) * KCODES + kt * 64 + lcol];
            }
            __syncthreads();
#pragma unroll
            for (int c = 0; c < 32; c++) {
                float4 a  = *(const float4*)&As[c][ty * 4];
                float4 bq = *(const float4*)&Bs[c][tx * 4];
                acc[0][0] = fmaf(a.x, bq.x, acc[0][0]);
                acc[0][1] = fmaf(a.x, bq.y, acc[0][1]);
                acc[0][2] = fmaf(a.x, bq.z, acc[0][2]);
                acc[0][3] = fmaf(a.x, bq.w, acc[0][3]);
                acc[1][0] = fmaf(a.y, bq.x, acc[1][0]);
                acc[1][1] = fmaf(a.y, bq.y, acc[1][1]);
                acc[1][2] = fmaf(a.y, bq.z, acc[1][2]);
                acc[1][3] = fmaf(a.y, bq.w, acc[1][3]);
                acc[2][0] = fmaf(a.z, bq.x, acc[2][0]);
                acc[2][1] = fmaf(a.z, bq.y, acc[2][1]);
                acc[2][2] = fmaf(a.z, bq.z, acc[2][2]);
                acc[2][3] = fmaf(a.z, bq.w, acc[2][3]);
                acc[3][0] = fmaf(a.w, bq.x, acc[3][0]);
                acc[3][1] = fmaf(a.w, bq.y, acc[3][1]);
                acc[3][2] = fmaf(a.w, bq.z, acc[3][2]);
                acc[3][3] = fmaf(a.w, bq.w, acc[3][3]);
            }
            __syncthreads();
        }

        // epilogue: running argmin (ascending k order -> first-min semantics)
#pragma unroll
        for (int j = 0; j < 4; j++) {
            int k = kt * 64 + tx * 4 + j;
            float c2v = g_c2[k];
#pragma unroll
            for (int i = 0; i < 4; i++) {
                float d = fmaf(-2.0f, acc[i][j], c2v);
                if (d < best[i]) { best[i] = d; besti[i] = k; }
            }
        }
    }

    // cross-thread (tx) argmin reduce per pixel
#pragma unroll
    for (int i = 0; i < 4; i++) {
        rv[ty * 4 + i][tx] = best[i];
        ri[ty * 4 + i][tx] = besti[i];
    }
    __syncthreads();
    if (tid < 64) {
        float bv = 3.4e38f;
        int bi = 0x7fffffff;
#pragma unroll
        for (int t = 0; t < 16; t++) {
            float v = rv[tid][t];
            int id = ri[tid][t];
            if (v < bv || (v == bv && id < bi)) { bv = v; bi = id; }
        }
        g_inds[b * HWN + n0 + tid] = bi;
    }
}

// ---------------------------------------------------------------------------
// Gather: out[b][c][n] = codebook[ind[b][n]][c]; accumulate (q - x)^2.
// Block: 64 pixels x all 256 channels. Warps coalesced along n.
// ---------------------------------------------------------------------------
__global__ __launch_bounds__(256) void gather_loss(const float* __restrict__ x,
                                                   const float* __restrict__ cb,
                                                   float* __restrict__ out) {
    int t = blockIdx.x;
    int b  = t >> 6;
    int n0 = (t & 63) * 64;
    int nl = threadIdx.x & 63;
    int c0 = threadIdx.x >> 6;   // 0..3

    int idx = g_inds[b * HWN + n0 + nl];
    const float* crow = cb + (size_t)idx * CDIM;
    const float* xb   = x   + (size_t)b * CDIM * HWN + n0 + nl;
    float*       ob   = out + (size_t)b * CDIM * HWN + n0 + nl;

    float lsum = 0.0f;
#pragma unroll 8
    for (int i = 0; i < 64; i++) {
        int c = c0 + i * 4;
        float q  = __ldg(crow + c);
        float xv = xb[(size_t)c * HWN];
        ob[(size_t)c * HWN] = q;
        float d = q - xv;
        lsum += d * d;
    }
#pragma unroll
    for (int o = 16; o; o >>= 1) lsum += __shfl_xor_sync(0xffffffffu, lsum, o);
    __shared__ float ws[8];
    if ((threadIdx.x & 31) == 0) ws[threadIdx.x >> 5] = lsum;
    __syncthreads();
    if (threadIdx.x == 0) {
        float s = 0.0f;
#pragma unroll
        for (int w = 0; w < 8; w++) s += ws[w];
        atomicAdd(&g_loss, s);
    }
}

// ---------------------------------------------------------------------------
// Finalize: loss = sum / (B*N*C) * commitment_weight(=1)
// ---------------------------------------------------------------------------
__global__ void finalize_loss(float* __restrict__ out, int loss_off) {
    out[loss_off] = g_loss * (1.0f / (float)(BATCH * HWN * CDIM));
}

extern "C" void kernel_launch(void* const* d_in, const int* in_sizes, int n_in,
                              void* d_out, int out_size) {
    const float* x  = (const float*)d_in[0];   // [16, 256, 64, 64]
    const float* cb = (const float*)d_in[1];   // [1024, 256]
    float* out = (float*)d_out;                // [16*256*64*64] quantized + [1] loss

    prep_transpose<<<dim3(KCODES / 32, CDIM / 32), 256>>>(cb);
    prep_c2<<<KCODES, 32>>>(cb);
    gemm_argmin<<<dim3(HWN / 64, BATCH), 256>>>(x);
    gather_loss<<<BATCH * HWN / 64, 256>>>(x, cb, out);
    finalize_loss<<<1, 1>>>(out, out_size - 1);
}

// round 11
// speedup vs baseline: 1.0882x; 1.0882x over previous
#include <cuda_runtime.h>
#include <cstdint>

#define HWN   4096
#define CDIM  256
#define KCODES 1024
#define BATCH 16

// Device-global scratch (no allocations allowed in kernel_launch)
__device__ float g_ct[CDIM * KCODES];   // codebook transposed [c][k], 1 MB
__device__ float g_c2[KCODES];          // ||codebook_k||^2
__device__ int   g_inds[BATCH * HWN];   // argmin indices
__device__ float g_loss;                // loss accumulator

// ---------------------------------------------------------------------------
// Prep 1: tiled transpose codebook[k][c] -> g_ct[c][k]; also zero g_loss.
// ---------------------------------------------------------------------------
__global__ void prep_transpose(const float* __restrict__ cb) {
    __shared__ float tile[32][33];
    int k0 = blockIdx.x * 32;
    int c0 = blockIdx.y * 32;
    int tx = threadIdx.x & 31;
    int r0 = threadIdx.x >> 5;  // 0..7
#pragma unroll
    for (int i = 0; i < 4; i++) {
        int k = r0 + i * 8;
        tile[k][tx] = cb[(size_t)(k0 + k) * CDIM + c0 + tx];
    }
    __syncthreads();
#pragma unroll
    for (int i = 0; i < 4; i++) {
        int c = r0 + i * 8;
        g_ct[(size_t)(c0 + c) * KCODES + k0 + tx] = tile[tx][c];
    }
    if (blockIdx.x == 0 && blockIdx.y == 0 && threadIdx.x == 0) g_loss = 0.0f;
}

// ---------------------------------------------------------------------------
// Prep 2: c2[k] = sum_c codebook[k][c]^2   (one warp per code row)
// ---------------------------------------------------------------------------
__global__ void prep_c2(const float* __restrict__ cb) {
    int k = blockIdx.x;
    int lane = threadIdx.x;
    float s = 0.0f;
#pragma unroll
    for (int c = lane; c < CDIM; c += 32) {
        float v = cb[(size_t)k * CDIM + c];
        s += v * v;
    }
#pragma unroll
    for (int o = 16; o; o >>= 1) s += __shfl_xor_sync(0xffffffffu, s, o);
    if (lane == 0) g_c2[k] = s;
}

// ---------------------------------------------------------------------------
// Packed f32x2 helpers (sm_100-family base feature, valid at compute_103)
// ---------------------------------------------------------------------------
__device__ __forceinline__ uint64_t dup_f32x2(float v) {
    uint64_t r;
    asm("mov.b64 %0, {%1, %1};" : "=l"(r) : "f"(v));
    return r;
}
__device__ __forceinline__ void fma2(uint64_t& acc, uint64_t a, uint64_t b) {
    asm("fma.rn.f32x2 %0, %1, %2, %0;" : "+l"(acc) : "l"(a), "l"(b));
}
__device__ __forceinline__ void unpack2(uint64_t v, float& lo, float& hi) {
    asm("mov.b64 {%0, %1}, %2;" : "=f"(lo), "=f"(hi) : "l"(v));
}

// ---------------------------------------------------------------------------
// SGEMM + argmin with packed f32x2 FMA (2x fp32 pipe rate).
// Block: 256 threads, 64 pixels x all 1024 codes.
// Tiles: TM=64 px, TN=64 codes, TK=32 channels.
// Microtile: 4 pixels x 4 codes = 4 px x 2 packed code-pairs.
// d2[k] = c2[k] - 2*dot(x_n, c_k)  (||x||^2 constant per pixel)
// ---------------------------------------------------------------------------
__global__ __launch_bounds__(256) void gemm_argmin(const float* __restrict__ x) {
    __shared__ float As[32][64];
    __shared__ float Bs[32][64];
    __shared__ float rv[64][17];
    __shared__ int   ri[64][17];

    const int b  = blockIdx.y;
    const int n0 = blockIdx.x * 64;
    const int tid = threadIdx.x;
    const int tx = tid & 15;        // code dim (4 codes = 2 pairs each)
    const int ty = tid >> 4;        // pixel dim (4 px each)
    const int lcol = tid & 63;      // loader column
    const int lrow = tid >> 6;      // loader row base (0..3)

    const float* xb = x + (size_t)b * CDIM * HWN + n0;

    float best[4];
    int   besti[4];
#pragma unroll
    for (int i = 0; i < 4; i++) { best[i] = 3.4e38f; besti[i] = 0; }

    for (int kt = 0; kt < KCODES / 64; kt++) {
        uint64_t acc2[4][2];   // [pixel][code-pair], each = 2 packed fp32 dots
#pragma unroll
        for (int i = 0; i < 4; i++) { acc2[i][0] = 0ull; acc2[i][1] = 0ull; }

#pragma unroll 1
        for (int cc = 0; cc < CDIM; cc += 32) {
#pragma unroll
            for (int i = 0; i < 8; i++) {
                int r = lrow + i * 4;
                As[r][lcol] = xb[(size_t)(cc + r) * HWN + lcol];
                Bs[r][lcol] = g_ct[(size_t)(cc + r) * KCODES + kt * 64 + lcol];
            }
            __syncthreads();
#pragma unroll
            for (int c = 0; c < 32; c++) {
                float4 a = *(const float4*)&As[c][ty * 4];
                // two packed code-pairs, loaded as 64-bit (naturally packed)
                uint64_t b01 = *(const uint64_t*)&Bs[c][tx * 4];
                uint64_t b23 = *(const uint64_t*)&Bs[c][tx * 4 + 2];
                uint64_t ax = dup_f32x2(a.x);
                uint64_t ay = dup_f32x2(a.y);
                uint64_t az = dup_f32x2(a.z);
                uint64_t aw = dup_f32x2(a.w);
                fma2(acc2[0][0], ax, b01); fma2(acc2[0][1], ax, b23);
                fma2(acc2[1][0], ay, b01); fma2(acc2[1][1], ay, b23);
                fma2(acc2[2][0], az, b01); fma2(acc2[2][1], az, b23);
                fma2(acc2[3][0], aw, b01); fma2(acc2[3][1], aw, b23);
            }
            __syncthreads();
        }

        // epilogue: running argmin, ascending k order -> first-min semantics
#pragma unroll
        for (int j2 = 0; j2 < 2; j2++) {
            int k0 = kt * 64 + tx * 4 + j2 * 2;
            float c2lo = g_c2[k0];
            float c2hi = g_c2[k0 + 1];
#pragma unroll
            for (int i = 0; i < 4; i++) {
                float dl, dh;
                unpack2(acc2[i][j2], dl, dh);
                float d0 = fmaf(-2.0f, dl, c2lo);
                float d1 = fmaf(-2.0f, dh, c2hi);
                if (d0 < best[i]) { best[i] = d0; besti[i] = k0; }
                if (d1 < best[i]) { best[i] = d1; besti[i] = k0 + 1; }
            }
        }
    }

    // cross-thread (tx) argmin reduce per pixel
#pragma unroll
    for (int i = 0; i < 4; i++) {
        rv[ty * 4 + i][tx] = best[i];
        ri[ty * 4 + i][tx] = besti[i];
    }
    __syncthreads();
    if (tid < 64) {
        float bv = 3.4e38f;
        int bi = 0x7fffffff;
#pragma unroll
        for (int t = 0; t < 16; t++) {
            float v = rv[tid][t];
            int id = ri[tid][t];
            if (v < bv || (v == bv && id < bi)) { bv = v; bi = id; }
        }
        g_inds[b * HWN + n0 + tid] = bi;
    }
}

// ---------------------------------------------------------------------------
// Gather + loss: out[b][c][n] = codebook[ind][c]; accumulate (q - x)^2.
// float4 codebook reads (4x fewer L1 wavefronts than scalar gathers).
// ---------------------------------------------------------------------------
__global__ __launch_bounds__(256) void gather_loss(const float* __restrict__ x,
                                                   const float* __restrict__ cb,
                                                   float* __restrict__ out) {
    int t = blockIdx.x;
    int b  = t >> 6;
    int n0 = (t & 63) * 64;
    int nl = threadIdx.x & 63;
    int c0 = (threadIdx.x >> 6) * 64;

    int idx = g_inds[b * HWN + n0 + nl];
    const float4* crow = (const float4*)(cb + (size_t)idx * CDIM + c0);
    const float* xb = x   + ((size_t)b * CDIM + c0) * HWN + n0 + nl;
    float*       ob = out + ((size_t)b * CDIM + c0) * HWN + n0 + nl;

    float lsum = 0.0f;
#pragma unroll 4
    for (int i = 0; i < 16; i++) {
        float4 q = __ldg(crow + i);
        float qv[4] = {q.x, q.y, q.z, q.w};
#pragma unroll
        for (int u = 0; u < 4; u++) {
            size_t off = (size_t)(i * 4 + u) * HWN;
            float xv = xb[off];
            ob[off] = qv[u];
            float d = qv[u] - xv;
            lsum = fmaf(d, d, lsum);
        }
    }
#pragma unroll
    for (int o = 16; o; o >>= 1) lsum += __shfl_xor_sync(0xffffffffu, lsum, o);
    __shared__ float ws[8];
    if ((threadIdx.x & 31) == 0) ws[threadIdx.x >> 5] = lsum;
    __syncthreads();
    if (threadIdx.x == 0) {
        float s = 0.0f;
#pragma unroll
        for (int w = 0; w < 8; w++) s += ws[w];
        atomicAdd(&g_loss, s);
    }
}

// ---------------------------------------------------------------------------
// Finalize: loss = sum / (B*N*C) * commitment_weight(=1)
// ---------------------------------------------------------------------------
__global__ void finalize_loss(float* __restrict__ out, int loss_off) {
    out[loss_off] = g_loss * (1.0f / (float)(BATCH * HWN * CDIM));
}

extern "C" void kernel_launch(void* const* d_in, const int* in_sizes, int n_in,
                              void* d_out, int out_size) {
    const float* x  = (const float*)d_in[0];   // [16, 256, 64, 64]
    const float* cb = (const float*)d_in[1];   // [1024, 256]
    float* out = (float*)d_out;                // quantized + [1] loss

    prep_transpose<<<dim3(KCODES / 32, CDIM / 32), 256>>>(cb);
    prep_c2<<<KCODES, 32>>>(cb);
    gemm_argmin<<<dim3(HWN / 64, BATCH), 256>>>(x);
    gather_loss<<<BATCH * HWN / 64, 256>>>(x, cb, out);
    finalize_loss<<<1, 1>>>(out, out_size - 1);
}

// round 12
// speedup vs baseline: 1.1966x; 1.0997x over previous
#include <cuda_runtime.h>
#include <cuda_bf16.h>
#include <cstdint>

#define HWN    4096
#define CDIM   256
#define KCODES 1024
#define BATCH  16
#define NPIX   (BATCH * HWN)
#define MARGIN 0.03f

// ---------------------------------------------------------------------------
// Device-global scratch
// ---------------------------------------------------------------------------
__device__ __align__(16) __nv_bfloat16 g_Ah[NPIX * CDIM];     // 32 MB x h-split
__device__ __align__(16) __nv_bfloat16 g_Al[NPIX * CDIM];     // 32 MB x l-split
__device__ __align__(16) __nv_bfloat16 g_cbh[KCODES * CDIM];  // codebook h
__device__ __align__(16) __nv_bfloat16 g_cbl[KCODES * CDIM];  // codebook l
__device__ float g_ct[CDIM * KCODES];   // codebook transposed (exact fixup)
__device__ float g_c2[KCODES];
__device__ int   g_inds[NPIX];
__device__ int   g_flag[NPIX];
__device__ int   g_nflag;
__device__ float g_loss;

// ---------------------------------------------------------------------------
// split2: v = h + l + O(2^-18 |v|)
// ---------------------------------------------------------------------------
__device__ __forceinline__ void split2(float v, uint16_t& h, uint16_t& l) {
    __nv_bfloat16 bh = __float2bfloat16_rn(v);
    __nv_bfloat16 bl = __float2bfloat16_rn(v - __bfloat162float(bh));
    h = __bfloat16_as_ushort(bh);
    l = __bfloat16_as_ushort(bl);
}

// ---------------------------------------------------------------------------
// Prep: transpose codebook -> g_ct (for exact fixup); zero loss + flag count
// ---------------------------------------------------------------------------
__global__ void prep_transpose(const float* __restrict__ cb) {
    __shared__ float tile[32][33];
    int k0 = blockIdx.x * 32, c0 = blockIdx.y * 32;
    int tx = threadIdx.x & 31, r0 = threadIdx.x >> 5;
#pragma unroll
    for (int i = 0; i < 4; i++)
        tile[r0 + i * 8][tx] = cb[(size_t)(k0 + r0 + i * 8) * CDIM + c0 + tx];
    __syncthreads();
#pragma unroll
    for (int i = 0; i < 4; i++)
        g_ct[(size_t)(c0 + r0 + i * 8) * KCODES + k0 + tx] = tile[tx][r0 + i * 8];
    if (blockIdx.x == 0 && blockIdx.y == 0 && threadIdx.x == 0) {
        g_loss = 0.0f;
        g_nflag = 0;
    }
}

__global__ void prep_c2(const float* __restrict__ cb) {
    int k = blockIdx.x, lane = threadIdx.x;
    float s = 0.0f;
#pragma unroll
    for (int c = lane; c < CDIM; c += 32) {
        float v = cb[(size_t)k * CDIM + c];
        s += v * v;
    }
#pragma unroll
    for (int o = 16; o; o >>= 1) s += __shfl_xor_sync(0xffffffffu, s, o);
    if (lane == 0) g_c2[k] = s;
}

// ---------------------------------------------------------------------------
// split_cb: codebook fp32 -> bf16 h/l, natural [k][c] layout
// ---------------------------------------------------------------------------
__global__ __launch_bounds__(256) void split_cb(const float* __restrict__ cb) {
    int i = blockIdx.x * 256 + threadIdx.x;   // grid covers 1024*256
    float v = cb[i];
    uint16_t h, l;
    split2(v, h, l);
    g_cbh[i] = __ushort_as_bfloat16(h);
    g_cbl[i] = __ushort_as_bfloat16(l);
}

// ---------------------------------------------------------------------------
// split_x: x[b][c][n] fp32 -> Ah/Al[(b*4096+n)][c] bf16 (transpose + split)
// ---------------------------------------------------------------------------
__global__ __launch_bounds__(256) void split_x(const float* __restrict__ x) {
    __shared__ float tile[64][33];
    int n0 = blockIdx.x * 64, c0 = blockIdx.y * 32, b = blockIdx.z;
    int tid = threadIdx.x;
    int nn = tid & 63, cb_ = tid >> 6;
#pragma unroll
    for (int i = 0; i < 8; i++) {
        int cl = cb_ + i * 4;
        tile[nn][cl] = x[(size_t)(b * CDIM + c0 + cl) * HWN + n0 + nn];
    }
    __syncthreads();
    int pl = tid >> 2, quad = tid & 3;
    size_t base = (size_t)(b * HWN + n0 + pl) * CDIM + c0 + quad * 8;
    uint32_t hw[4], lw[4];
#pragma unroll
    for (int u = 0; u < 4; u++) {
        uint16_t h0, l0, h1, l1;
        split2(tile[pl][quad * 8 + u * 2 + 0], h0, l0);
        split2(tile[pl][quad * 8 + u * 2 + 1], h1, l1);
        hw[u] = (uint32_t)h0 | ((uint32_t)h1 << 16);
        lw[u] = (uint32_t)l0 | ((uint32_t)l1 << 16);
    }
    *(uint4*)(g_Ah + base) = make_uint4(hw[0], hw[1], hw[2], hw[3]);
    *(uint4*)(g_Al + base) = make_uint4(lw[0], lw[1], lw[2], lw[3]);
}

// ---------------------------------------------------------------------------
// HMMA m16n8k16 bf16 -> fp32
// ---------------------------------------------------------------------------
__device__ __forceinline__ void mma16816(float* d, uint32_t a0, uint32_t a1,
                                         uint32_t a2, uint32_t a3,
                                         uint32_t b0, uint32_t b1) {
    asm volatile(
        "mma.sync.aligned.m16n8k16.row.col.f32.bf16.bf16.f32 "
        "{%0,%1,%2,%3}, {%4,%5,%6,%7}, {%8,%9}, {%0,%1,%2,%3};"
        : "+f"(d[0]), "+f"(d[1]), "+f"(d[2]), "+f"(d[3])
        : "r"(a0), "r"(a1), "r"(a2), "r"(a3), "r"(b0), "r"(b1));
}

// ---------------------------------------------------------------------------
// Tensor-core approximate GEMM + top-2 argmin + flagging.
// CTA: 128 pixels x 1024 codes. 8 warps: warpM = wid&1 (64 px), warpN = wid>>1
// (32 codes per 128-code N-tile). Warp tile 64x32, k-chunks of 64.
// dot ~= xh*ch + xh*cl + xl*ch ; d2 = c2 - 2*dot
// ---------------------------------------------------------------------------
#define APITCH 528             // 256*2 + 16 pad (bytes)
#define BPITCH 144             // 64*2 + 16 pad
#define OFF_AH 0
#define OFF_AL (128 * APITCH)                 //  67584
#define OFF_BH (2 * 128 * APITCH)             // 135168
#define OFF_BL (OFF_BH + 128 * BPITCH)        // 153600
#define OFF_C2 (OFF_BL + 128 * BPITCH)        // 172032
#define OFF_RB (OFF_C2 + 4096)                // 176128
#define OFF_RS (OFF_RB + 2048)
#define OFF_RI (OFF_RS + 2048)
#define SMEM_GEMM (OFF_RI + 2048)             // 182272

__global__ __launch_bounds__(256, 1) void gemm_mma(void) {
    extern __shared__ __align__(16) unsigned char smem[];
    const int tid = threadIdx.x;
    const int wid = tid >> 5, lane = tid & 31;
    const int g = lane >> 2, tig = lane & 3;
    const int warpM = wid & 1, warpN = wid >> 1;

    // ---- stage A (both splits) resident: 128 px x 256 ch ----
    {
        const __nv_bfloat16* srcs[2] = {g_Ah, g_Al};
        const int offs[2] = {OFF_AH, OFF_AL};
#pragma unroll
        for (int s = 0; s < 2; s++) {
            const uint4* src = (const uint4*)(srcs[s] + (size_t)blockIdx.x * 128 * CDIM);
#pragma unroll
            for (int i = 0; i < 16; i++) {
                int idx = tid + i * 256;          // 4096 uint4
                int r = idx >> 5, c16 = idx & 31;
                *(uint4*)(smem + offs[s] + r * APITCH + c16 * 16) = src[idx];
            }
        }
#pragma unroll
        for (int i = 0; i < 4; i++)
            ((float*)(smem + OFF_C2))[tid + i * 256] = g_c2[tid + i * 256];
    }
    __syncthreads();

    // per-lane top-2 state for 8 rows
    float bestv[8], secv[8];
    int bidx[8];
#pragma unroll
    for (int r = 0; r < 8; r++) { bestv[r] = 3.4e38f; secv[r] = 3.4e38f; bidx[r] = 0; }

    const float* c2s = (const float*)(smem + OFF_C2);

#pragma unroll 1
    for (int nt = 0; nt < 8; nt++) {
        float acc[4][4][4];
#pragma unroll
        for (int mi = 0; mi < 4; mi++)
#pragma unroll
            for (int ni = 0; ni < 4; ni++)
#pragma unroll
                for (int e = 0; e < 4; e++) acc[mi][ni][e] = 0.0f;

#pragma unroll 1
        for (int kc = 0; kc < 4; kc++) {
            // ---- load B chunk: 128 codes x 64 ch, both splits ----
            __syncthreads();
            {
                const __nv_bfloat16* srcs[2] = {g_cbh, g_cbl};
                const int offs[2] = {OFF_BH, OFF_BL};
#pragma unroll
                for (int s = 0; s < 2; s++) {
                    const uint4* src = (const uint4*)srcs[s];
#pragma unroll
                    for (int i = 0; i < 4; i++) {
                        int idx = tid + i * 256;      // 1024 uint4
                        int r = idx >> 3, q = idx & 7;
                        *(uint4*)(smem + offs[s] + r * BPITCH + q * 16) =
                            src[(nt * 128 + r) * 32 + kc * 8 + q];
                    }
                }
            }
            __syncthreads();

            // ---- 3 products x 4 k-steps of 16 ----
#pragma unroll 1
            for (int p = 0; p < 3; p++) {
                const unsigned char* As = smem + (p == 2 ? OFF_AL : OFF_AH);
                const unsigned char* Bs = smem + (p == 1 ? OFF_BL : OFF_BH);
#pragma unroll
                for (int ks = 0; ks < 4; ks++) {
                    int k0 = kc * 64 + ks * 16;       // A channel base
                    int l0 = ks * 16;                 // B chunk-local base
                    uint32_t af[4][4];
#pragma unroll
                    for (int mi = 0; mi < 4; mi++) {
                        int row = warpM * 64 + mi * 16 + g;
                        const unsigned char* pr0 = As + row * APITCH + (k0 + tig * 2) * 2;
                        const unsigned char* pr1 = As + (row + 8) * APITCH + (k0 + tig * 2) * 2;
                        af[mi][0] = *(const uint32_t*)pr0;
                        af[mi][1] = *(const uint32_t*)pr1;
                        af[mi][2] = *(const uint32_t*)(pr0 + 16);
                        af[mi][3] = *(const uint32_t*)(pr1 + 16);
                    }
                    uint32_t bf[4][2];
#pragma unroll
                    for (int ni = 0; ni < 4; ni++) {
                        int code = warpN * 32 + ni * 8 + g;
                        const unsigned char* pb = Bs + code * BPITCH + (l0 + tig * 2) * 2;
                        bf[ni][0] = *(const uint32_t*)pb;
                        bf[ni][1] = *(const uint32_t*)(pb + 16);
                    }
#pragma unroll
                    for (int mi = 0; mi < 4; mi++)
#pragma unroll
                        for (int ni = 0; ni < 4; ni++)
                            mma16816(acc[mi][ni], af[mi][0], af[mi][1], af[mi][2],
                                     af[mi][3], bf[ni][0], bf[ni][1]);
                }
            }
        }

        // ---- epilogue: fold into per-lane top-2 (ascending col order) ----
#pragma unroll
        for (int ni = 0; ni < 4; ni++) {
            int cg = nt * 128 + warpN * 32 + ni * 8 + tig * 2;
            float c20 = c2s[cg], c21 = c2s[cg + 1];
#pragma unroll
            for (int mi = 0; mi < 4; mi++) {
#pragma unroll
                for (int e = 0; e < 4; e++) {
                    int r8 = mi * 2 + (e >> 1);       // row slot: g or g+8
                    float v = fmaf(-2.0f, acc[mi][ni][e], (e & 1) ? c21 : c20);
                    int k = cg + (e & 1);
                    if (v < bestv[r8]) {
                        secv[r8] = bestv[r8];
                        bestv[r8] = v;
                        bidx[r8] = k;
                    } else if (v < secv[r8]) {
                        secv[r8] = v;
                    }
                }
            }
        }
    }

    // ---- quad merge (lanes sharing rows: same g, tig = 0..3) ----
#pragma unroll
    for (int o = 1; o <= 2; o <<= 1) {
#pragma unroll
        for (int r = 0; r < 8; r++) {
            float ob = __shfl_xor_sync(0xffffffffu, bestv[r], o);
            float os = __shfl_xor_sync(0xffffffffu, secv[r], o);
            int oi = __shfl_xor_sync(0xffffffffu, bidx[r], o);
            bool take = (ob < bestv[r]) || (ob == bestv[r] && oi < bidx[r]);
            float loser = take ? bestv[r] : ob;
            if (take) { bestv[r] = ob; bidx[r] = oi; }
            float ns = fminf(secv[r], os);
            secv[r] = fminf(ns, loser);
        }
    }

    float* redb = (float*)(smem + OFF_RB);
    float* reds = (float*)(smem + OFF_RS);
    int*   redi = (int*)(smem + OFF_RI);
    if (tig == 0) {
#pragma unroll
        for (int r8 = 0; r8 < 8; r8++) {
            int row = warpM * 64 + (r8 >> 1) * 16 + (r8 & 1) * 8 + g;
            redb[warpN * 128 + row] = bestv[r8];
            reds[warpN * 128 + row] = secv[r8];
            redi[warpN * 128 + row] = bidx[r8];
        }
    }
    __syncthreads();

    if (tid < 128) {
        float bv = 3.4e38f, sv = 3.4e38f;
        int bi = 0x7fffffff;
#pragma unroll
        for (int w = 0; w < 4; w++) {
            float ob = redb[w * 128 + tid];
            float os = reds[w * 128 + tid];
            int oi = redi[w * 128 + tid];
            bool take = (ob < bv) || (ob == bv && oi < bi);
            float loser = take ? bv : ob;
            if (take) { bv = ob; bi = oi; }
            sv = fminf(fminf(sv, os), loser);
        }
        int pixel = blockIdx.x * 128 + tid;
        g_inds[pixel] = bi;
        if (sv - bv < MARGIN) {
            int slot = atomicAdd(&g_nflag, 1);
            g_flag[slot] = pixel;
        }
    }
}

// ---------------------------------------------------------------------------
// Exact fp32 fixup for flagged pixels: full 1024-code scalar argmin
// (round-4 machinery over a gathered pixel list). Fixed grid; early-exit.
// ---------------------------------------------------------------------------
__global__ __launch_bounds__(256) void fixup(const float* __restrict__ x) {
    int nflag = g_nflag;
    int base = blockIdx.x * 64;
    if (base >= nflag) return;

    __shared__ float As[32][64];
    __shared__ float Bs[32][64];
    __shared__ float rv[64][17];
    __shared__ int   ri[64][17];
    __shared__ int   pid[64];
    __shared__ size_t pbase[64];

    const int tid = threadIdx.x;
    if (tid < 64) {
        int p = g_flag[(base + tid < nflag) ? base + tid : base];
        pid[tid] = p;
        pbase[tid] = (size_t)(p >> 12) * CDIM * HWN + (p & 4095);
    }
    __syncthreads();

    const int tx = tid & 15, ty = tid >> 4;
    const int lcol = tid & 63, lrow = tid >> 6;
    const size_t mybase = pbase[lcol];

    float best[4];
    int   besti[4];
#pragma unroll
    for (int i = 0; i < 4; i++) { best[i] = 3.4e38f; besti[i] = 0; }

    for (int kt = 0; kt < KCODES / 64; kt++) {
        float acc[4][4];
#pragma unroll
        for (int i = 0; i < 4; i++)
#pragma unroll
            for (int j = 0; j < 4; j++) acc[i][j] = 0.0f;

#pragma unroll 1
        for (int cc = 0; cc < CDIM; cc += 32) {
#pragma unroll
            for (int i = 0; i < 8; i++) {
                int r = lrow + i * 4;
                As[r][lcol] = x[mybase + (size_t)(cc + r) * HWN];
                Bs[r][lcol] = g_ct[(size_t)(cc + r) * KCODES + kt * 64 + lcol];
            }
            __syncthreads();
#pragma unroll
            for (int c = 0; c < 32; c++) {
                float4 a  = *(const float4*)&As[c][ty * 4];
                float4 bq = *(const float4*)&Bs[c][tx * 4];
                acc[0][0] = fmaf(a.x, bq.x, acc[0][0]);
                acc[0][1] = fmaf(a.x, bq.y, acc[0][1]);
                acc[0][2] = fmaf(a.x, bq.z, acc[0][2]);
                acc[0][3] = fmaf(a.x, bq.w, acc[0][3]);
                acc[1][0] = fmaf(a.y, bq.x, acc[1][0]);
                acc[1][1] = fmaf(a.y, bq.y, acc[1][1]);
                acc[1][2] = fmaf(a.y, bq.z, acc[1][2]);
                acc[1][3] = fmaf(a.y, bq.w, acc[1][3]);
                acc[2][0] = fmaf(a.z, bq.x, acc[2][0]);
                acc[2][1] = fmaf(a.z, bq.y, acc[2][1]);
                acc[2][2] = fmaf(a.z, bq.z, acc[2][2]);
                acc[2][3] = fmaf(a.z, bq.w, acc[2][3]);
                acc[3][0] = fmaf(a.w, bq.x, acc[3][0]);
                acc[3][1] = fmaf(a.w, bq.y, acc[3][1]);
                acc[3][2] = fmaf(a.w, bq.z, acc[3][2]);
                acc[3][3] = fmaf(a.w, bq.w, acc[3][3]);
            }
            __syncthreads();
        }
#pragma unroll
        for (int j = 0; j < 4; j++) {
            int k = kt * 64 + tx * 4 + j;
            float c2v = g_c2[k];
#pragma unroll
            for (int i = 0; i < 4; i++) {
                float d = fmaf(-2.0f, acc[i][j], c2v);
                if (d < best[i]) { best[i] = d; besti[i] = k; }
            }
        }
    }

#pragma unroll
    for (int i = 0; i < 4; i++) {
        rv[ty * 4 + i][tx] = best[i];
        ri[ty * 4 + i][tx] = besti[i];
    }
    __syncthreads();
    if (tid < 64) {
        float bv = 3.4e38f;
        int bi = 0x7fffffff;
#pragma unroll
        for (int t = 0; t < 16; t++) {
            float v = rv[tid][t];
            int id = ri[tid][t];
            if (v < bv || (v == bv && id < bi)) { bv = v; bi = id; }
        }
        g_inds[pid[tid]] = bi;   // duplicates write identical values
    }
}

// ---------------------------------------------------------------------------
// Gather + loss (float4 codebook reads)
// ---------------------------------------------------------------------------
__global__ __launch_bounds__(256) void gather_loss(const float* __restrict__ x,
                                                   const float* __restrict__ cb,
                                                   float* __restrict__ out) {
    int t = blockIdx.x;
    int b  = t >> 6;
    int n0 = (t & 63) * 64;
    int nl = threadIdx.x & 63;
    int c0 = (threadIdx.x >> 6) * 64;

    int idx = g_inds[b * HWN + n0 + nl];
    const float4* crow = (const float4*)(cb + (size_t)idx * CDIM + c0);
    const float* xb = x   + ((size_t)b * CDIM + c0) * HWN + n0 + nl;
    float*       ob = out + ((size_t)b * CDIM + c0) * HWN + n0 + nl;

    float lsum = 0.0f;
#pragma unroll 4
    for (int i = 0; i < 16; i++) {
        float4 q = __ldg(crow + i);
        float qv[4] = {q.x, q.y, q.z, q.w};
#pragma unroll
        for (int u = 0; u < 4; u++) {
            size_t off = (size_t)(i * 4 + u) * HWN;
            float xv = xb[off];
            ob[off] = qv[u];
            float d = qv[u] - xv;
            lsum = fmaf(d, d, lsum);
        }
    }
#pragma unroll
    for (int o = 16; o; o >>= 1) lsum += __shfl_xor_sync(0xffffffffu, lsum, o);
    __shared__ float ws[8];
    if ((threadIdx.x & 31) == 0) ws[threadIdx.x >> 5] = lsum;
    __syncthreads();
    if (threadIdx.x == 0) {
        float s = 0.0f;
#pragma unroll
        for (int w = 0; w < 8; w++) s += ws[w];
        atomicAdd(&g_loss, s);
    }
}

__global__ void finalize_loss(float* __restrict__ out, int loss_off) {
    out[loss_off] = g_loss * (1.0f / (float)((size_t)BATCH * HWN * CDIM));
}

// ---------------------------------------------------------------------------
extern "C" void kernel_launch(void* const* d_in, const int* in_sizes, int n_in,
                              void* d_out, int out_size) {
    const float* x  = (const float*)d_in[0];   // [16, 256, 64, 64]
    const float* cb = (const float*)d_in[1];   // [1024, 256]
    float* out = (float*)d_out;

    cudaFuncSetAttribute(gemm_mma, cudaFuncAttributeMaxDynamicSharedMemorySize,
                         SMEM_GEMM);

    prep_transpose<<<dim3(KCODES / 32, CDIM / 32), 256>>>(cb);
    prep_c2<<<KCODES, 32>>>(cb);
    split_cb<<<KCODES * CDIM / 256, 256>>>(cb);
    split_x<<<dim3(HWN / 64, CDIM / 32, BATCH), 256>>>(x);
    gemm_mma<<<NPIX / 128, 256, SMEM_GEMM>>>();
    fixup<<<1024, 256>>>(x);
    gather_loss<<<BATCH * HWN / 64, 256>>>(x, cb, out);
    finalize_loss<<<1, 1>>>(out, out_size - 1);
}

// round 13
// speedup vs baseline: 1.1970x; 1.0003x over previous
#include <cuda_runtime.h>
#include <cuda_bf16.h>
#include <cstdint>

#define HWN    4096
#define CDIM   256
#define KCODES 1024
#define BATCH  16
#define NPIX   (BATCH * HWN)
#define MARGIN 0.03f

// ---------------------------------------------------------------------------
// Device-global scratch
// ---------------------------------------------------------------------------
__device__ __align__(16) __nv_bfloat16 g_Ah[NPIX * CDIM];     // 32 MB x h-split
__device__ __align__(16) __nv_bfloat16 g_Al[NPIX * CDIM];     // 32 MB x l-split
__device__ __align__(16) __nv_bfloat16 g_cbh[KCODES * CDIM];  // codebook h
__device__ __align__(16) __nv_bfloat16 g_cbl[KCODES * CDIM];  // codebook l
__device__ float g_ct[CDIM * KCODES];   // codebook transposed (exact fixup)
__device__ float g_c2[KCODES];
__device__ int   g_inds[NPIX];
__device__ int   g_flag[NPIX];
__device__ int   g_nflag;
__device__ float g_loss;

// ---------------------------------------------------------------------------
// split2: v = h + l + O(2^-18 |v|)
// ---------------------------------------------------------------------------
__device__ __forceinline__ void split2(float v, uint16_t& h, uint16_t& l) {
    __nv_bfloat16 bh = __float2bfloat16_rn(v);
    __nv_bfloat16 bl = __float2bfloat16_rn(v - __bfloat162float(bh));
    h = __bfloat16_as_ushort(bh);
    l = __bfloat16_as_ushort(bl);
}

// ---------------------------------------------------------------------------
// Prep: transpose codebook -> g_ct (for exact fixup); zero loss + flag count
// ---------------------------------------------------------------------------
__global__ void prep_transpose(const float* __restrict__ cb) {
    __shared__ float tile[32][33];
    int k0 = blockIdx.x * 32, c0 = blockIdx.y * 32;
    int tx = threadIdx.x & 31, r0 = threadIdx.x >> 5;
#pragma unroll
    for (int i = 0; i < 4; i++)
        tile[r0 + i * 8][tx] = cb[(size_t)(k0 + r0 + i * 8) * CDIM + c0 + tx];
    __syncthreads();
#pragma unroll
    for (int i = 0; i < 4; i++)
        g_ct[(size_t)(c0 + r0 + i * 8) * KCODES + k0 + tx] = tile[tx][r0 + i * 8];
    if (blockIdx.x == 0 && blockIdx.y == 0 && threadIdx.x == 0) {
        g_loss = 0.0f;
        g_nflag = 0;
    }
}

__global__ void prep_c2(const float* __restrict__ cb) {
    int k = blockIdx.x, lane = threadIdx.x;
    float s = 0.0f;
#pragma unroll
    for (int c = lane; c < CDIM; c += 32) {
        float v = cb[(size_t)k * CDIM + c];
        s += v * v;
    }
#pragma unroll
    for (int o = 16; o; o >>= 1) s += __shfl_xor_sync(0xffffffffu, s, o);
    if (lane == 0) g_c2[k] = s;
}

// ---------------------------------------------------------------------------
// split_cb: codebook fp32 -> bf16 h/l, natural [k][c] layout
// ---------------------------------------------------------------------------
__global__ __launch_bounds__(256) void split_cb(const float* __restrict__ cb) {
    int i = blockIdx.x * 256 + threadIdx.x;   // grid covers 1024*256
    float v = cb[i];
    uint16_t h, l;
    split2(v, h, l);
    g_cbh[i] = __ushort_as_bfloat16(h);
    g_cbl[i] = __ushort_as_bfloat16(l);
}

// ---------------------------------------------------------------------------
// split_x: x[b][c][n] fp32 -> Ah/Al[(b*4096+n)][c] bf16 (transpose + split)
// ---------------------------------------------------------------------------
__global__ __launch_bounds__(256) void split_x(const float* __restrict__ x) {
    __shared__ float tile[64][33];
    int n0 = blockIdx.x * 64, c0 = blockIdx.y * 32, b = blockIdx.z;
    int tid = threadIdx.x;
    int nn = tid & 63, cb_ = tid >> 6;
#pragma unroll
    for (int i = 0; i < 8; i++) {
        int cl = cb_ + i * 4;
        tile[nn][cl] = x[(size_t)(b * CDIM + c0 + cl) * HWN + n0 + nn];
    }
    __syncthreads();
    int pl = tid >> 2, quad = tid & 3;
    size_t base = (size_t)(b * HWN + n0 + pl) * CDIM + c0 + quad * 8;
    uint32_t hw[4], lw[4];
#pragma unroll
    for (int u = 0; u < 4; u++) {
        uint16_t h0, l0, h1, l1;
        split2(tile[pl][quad * 8 + u * 2 + 0], h0, l0);
        split2(tile[pl][quad * 8 + u * 2 + 1], h1, l1);
        hw[u] = (uint32_t)h0 | ((uint32_t)h1 << 16);
        lw[u] = (uint32_t)l0 | ((uint32_t)l1 << 16);
    }
    *(uint4*)(g_Ah + base) = make_uint4(hw[0], hw[1], hw[2], hw[3]);
    *(uint4*)(g_Al + base) = make_uint4(lw[0], lw[1], lw[2], lw[3]);
}

// ---------------------------------------------------------------------------
// HMMA m16n8k16 bf16 -> fp32
// ---------------------------------------------------------------------------
__device__ __forceinline__ void mma16816(float* d, uint32_t a0, uint32_t a1,
                                         uint32_t a2, uint32_t a3,
                                         uint32_t b0, uint32_t b1) {
    asm volatile(
        "mma.sync.aligned.m16n8k16.row.col.f32.bf16.bf16.f32 "
        "{%0,%1,%2,%3}, {%4,%5,%6,%7}, {%8,%9}, {%0,%1,%2,%3};"
        : "+f"(d[0]), "+f"(d[1]), "+f"(d[2]), "+f"(d[3])
        : "r"(a0), "r"(a1), "r"(a2), "r"(a3), "r"(b0), "r"(b1));
}

// ---------------------------------------------------------------------------
// Tensor-core approximate GEMM + top-2 argmin + flagging.
// CTA: 128 pixels x 1024 codes. 8 warps: warpM = wid&1 (64 px), warpN = wid>>1
// (32 codes per 128-code N-tile). Warp tile 64x32, k-chunks of 64.
// dot ~= xh*ch + xh*cl + xl*ch ; d2 = c2 - 2*dot
// ---------------------------------------------------------------------------
#define APITCH 528             // 256*2 + 16 pad (bytes)
#define BPITCH 144             // 64*2 + 16 pad
#define OFF_AH 0
#define OFF_AL (128 * APITCH)                 //  67584
#define OFF_BH (2 * 128 * APITCH)             // 135168
#define OFF_BL (OFF_BH + 128 * BPITCH)        // 153600
#define OFF_C2 (OFF_BL + 128 * BPITCH)        // 172032
#define OFF_RB (OFF_C2 + 4096)                // 176128
#define OFF_RS (OFF_RB + 2048)
#define OFF_RI (OFF_RS + 2048)
#define SMEM_GEMM (OFF_RI + 2048)             // 182272

__global__ __launch_bounds__(256, 1) void gemm_mma(void) {
    extern __shared__ __align__(16) unsigned char smem[];
    const int tid = threadIdx.x;
    const int wid = tid >> 5, lane = tid & 31;
    const int g = lane >> 2, tig = lane & 3;
    const int warpM = wid & 1, warpN = wid >> 1;

    // ---- stage A (both splits) resident: 128 px x 256 ch ----
    {
        const __nv_bfloat16* srcs[2] = {g_Ah, g_Al};
        const int offs[2] = {OFF_AH, OFF_AL};
#pragma unroll
        for (int s = 0; s < 2; s++) {
            const uint4* src = (const uint4*)(srcs[s] + (size_t)blockIdx.x * 128 * CDIM);
#pragma unroll
            for (int i = 0; i < 16; i++) {
                int idx = tid + i * 256;          // 4096 uint4
                int r = idx >> 5, c16 = idx & 31;
                *(uint4*)(smem + offs[s] + r * APITCH + c16 * 16) = src[idx];
            }
        }
#pragma unroll
        for (int i = 0; i < 4; i++)
            ((float*)(smem + OFF_C2))[tid + i * 256] = g_c2[tid + i * 256];
    }
    __syncthreads();

    // per-lane top-2 state for 8 rows
    float bestv[8], secv[8];
    int bidx[8];
#pragma unroll
    for (int r = 0; r < 8; r++) { bestv[r] = 3.4e38f; secv[r] = 3.4e38f; bidx[r] = 0; }

    const float* c2s = (const float*)(smem + OFF_C2);

#pragma unroll 1
    for (int nt = 0; nt < 8; nt++) {
        float acc[4][4][4];
#pragma unroll
        for (int mi = 0; mi < 4; mi++)
#pragma unroll
            for (int ni = 0; ni < 4; ni++)
#pragma unroll
                for (int e = 0; e < 4; e++) acc[mi][ni][e] = 0.0f;

#pragma unroll 1
        for (int kc = 0; kc < 4; kc++) {
            // ---- load B chunk: 128 codes x 64 ch, both splits ----
            __syncthreads();
            {
                const __nv_bfloat16* srcs[2] = {g_cbh, g_cbl};
                const int offs[2] = {OFF_BH, OFF_BL};
#pragma unroll
                for (int s = 0; s < 2; s++) {
                    const uint4* src = (const uint4*)srcs[s];
#pragma unroll
                    for (int i = 0; i < 4; i++) {
                        int idx = tid + i * 256;      // 1024 uint4
                        int r = idx >> 3, q = idx & 7;
                        *(uint4*)(smem + offs[s] + r * BPITCH + q * 16) =
                            src[(nt * 128 + r) * 32 + kc * 8 + q];
                    }
                }
            }
            __syncthreads();

            // ---- 3 products x 4 k-steps of 16 ----
#pragma unroll 1
            for (int p = 0; p < 3; p++) {
                const unsigned char* As = smem + (p == 2 ? OFF_AL : OFF_AH);
                const unsigned char* Bs = smem + (p == 1 ? OFF_BL : OFF_BH);
#pragma unroll
                for (int ks = 0; ks < 4; ks++) {
                    int k0 = kc * 64 + ks * 16;       // A channel base
                    int l0 = ks * 16;                 // B chunk-local base
                    uint32_t af[4][4];
#pragma unroll
                    for (int mi = 0; mi < 4; mi++) {
                        int row = warpM * 64 + mi * 16 + g;
                        const unsigned char* pr0 = As + row * APITCH + (k0 + tig * 2) * 2;
                        const unsigned char* pr1 = As + (row + 8) * APITCH + (k0 + tig * 2) * 2;
                        af[mi][0] = *(const uint32_t*)pr0;
                        af[mi][1] = *(const uint32_t*)pr1;
                        af[mi][2] = *(const uint32_t*)(pr0 + 16);
                        af[mi][3] = *(const uint32_t*)(pr1 + 16);
                    }
                    uint32_t bf[4][2];
#pragma unroll
                    for (int ni = 0; ni < 4; ni++) {
                        int code = warpN * 32 + ni * 8 + g;
                        const unsigned char* pb = Bs + code * BPITCH + (l0 + tig * 2) * 2;
                        bf[ni][0] = *(const uint32_t*)pb;
                        bf[ni][1] = *(const uint32_t*)(pb + 16);
                    }
#pragma unroll
                    for (int mi = 0; mi < 4; mi++)
#pragma unroll
                        for (int ni = 0; ni < 4; ni++)
                            mma16816(acc[mi][ni], af[mi][0], af[mi][1], af[mi][2],
                                     af[mi][3], bf[ni][0], bf[ni][1]);
                }
            }
        }

        // ---- epilogue: fold into per-lane top-2 (ascending col order) ----
#pragma unroll
        for (int ni = 0; ni < 4; ni++) {
            int cg = nt * 128 + warpN * 32 + ni * 8 + tig * 2;
            float c20 = c2s[cg], c21 = c2s[cg + 1];
#pragma unroll
            for (int mi = 0; mi < 4; mi++) {
#pragma unroll
                for (int e = 0; e < 4; e++) {
                    int r8 = mi * 2 + (e >> 1);       // row slot: g or g+8
                    float v = fmaf(-2.0f, acc[mi][ni][e], (e & 1) ? c21 : c20);
                    int k = cg + (e & 1);
                    if (v < bestv[r8]) {
                        secv[r8] = bestv[r8];
                        bestv[r8] = v;
                        bidx[r8] = k;
                    } else if (v < secv[r8]) {
                        secv[r8] = v;
                    }
                }
            }
        }
    }

    // ---- quad merge (lanes sharing rows: same g, tig = 0..3) ----
#pragma unroll
    for (int o = 1; o <= 2; o <<= 1) {
#pragma unroll
        for (int r = 0; r < 8; r++) {
            float ob = __shfl_xor_sync(0xffffffffu, bestv[r], o);
            float os = __shfl_xor_sync(0xffffffffu, secv[r], o);
            int oi = __shfl_xor_sync(0xffffffffu, bidx[r], o);
            bool take = (ob < bestv[r]) || (ob == bestv[r] && oi < bidx[r]);
            float loser = take ? bestv[r] : ob;
            if (take) { bestv[r] = ob; bidx[r] = oi; }
            float ns = fminf(secv[r], os);
            secv[r] = fminf(ns, loser);
        }
    }

    float* redb = (float*)(smem + OFF_RB);
    float* reds = (float*)(smem + OFF_RS);
    int*   redi = (int*)(smem + OFF_RI);
    if (tig == 0) {
#pragma unroll
        for (int r8 = 0; r8 < 8; r8++) {
            int row = warpM * 64 + (r8 >> 1) * 16 + (r8 & 1) * 8 + g;
            redb[warpN * 128 + row] = bestv[r8];
            reds[warpN * 128 + row] = secv[r8];
            redi[warpN * 128 + row] = bidx[r8];
        }
    }
    __syncthreads();

    if (tid < 128) {
        float bv = 3.4e38f, sv = 3.4e38f;
        int bi = 0x7fffffff;
#pragma unroll
        for (int w = 0; w < 4; w++) {
            float ob = redb[w * 128 + tid];
            float os = reds[w * 128 + tid];
            int oi = redi[w * 128 + tid];
            bool take = (ob < bv) || (ob == bv && oi < bi);
            float loser = take ? bv : ob;
            if (take) { bv = ob; bi = oi; }
            sv = fminf(fminf(sv, os), loser);
        }
        int pixel = blockIdx.x * 128 + tid;
        g_inds[pixel] = bi;
        if (sv - bv < MARGIN) {
            int slot = atomicAdd(&g_nflag, 1);
            g_flag[slot] = pixel;
        }
    }
}

// ---------------------------------------------------------------------------
// Exact fp32 fixup for flagged pixels: full 1024-code scalar argmin
// (round-4 machinery over a gathered pixel list). Fixed grid; early-exit.
// ---------------------------------------------------------------------------
__global__ __launch_bounds__(256) void fixup(const float* __restrict__ x) {
    int nflag = g_nflag;
    int base = blockIdx.x * 64;
    if (base >= nflag) return;

    __shared__ float As[32][64];
    __shared__ float Bs[32][64];
    __shared__ float rv[64][17];
    __shared__ int   ri[64][17];
    __shared__ int   pid[64];
    __shared__ size_t pbase[64];

    const int tid = threadIdx.x;
    if (tid < 64) {
        int p = g_flag[(base + tid < nflag) ? base + tid : base];
        pid[tid] = p;
        pbase[tid] = (size_t)(p >> 12) * CDIM * HWN + (p & 4095);
    }
    __syncthreads();

    const int tx = tid & 15, ty = tid >> 4;
    const int lcol = tid & 63, lrow = tid >> 6;
    const size_t mybase = pbase[lcol];

    float best[4];
    int   besti[4];
#pragma unroll
    for (int i = 0; i < 4; i++) { best[i] = 3.4e38f; besti[i] = 0; }

    for (int kt = 0; kt < KCODES / 64; kt++) {
        float acc[4][4];
#pragma unroll
        for (int i = 0; i < 4; i++)
#pragma unroll
            for (int j = 0; j < 4; j++) acc[i][j] = 0.0f;

#pragma unroll 1
        for (int cc = 0; cc < CDIM; cc += 32) {
#pragma unroll
            for (int i = 0; i < 8; i++) {
                int r = lrow + i * 4;
                As[r][lcol] = x[mybase + (size_t)(cc + r) * HWN];
                Bs[r][lcol] = g_ct[(size_t)(cc + r) * KCODES + kt * 64 + lcol];
            }
            __syncthreads();
#pragma unroll
            for (int c = 0; c < 32; c++) {
                float4 a  = *(const float4*)&As[c][ty * 4];
                float4 bq = *(const float4*)&Bs[c][tx * 4];
                acc[0][0] = fmaf(a.x, bq.x, acc[0][0]);
                acc[0][1] = fmaf(a.x, bq.y, acc[0][1]);
                acc[0][2] = fmaf(a.x, bq.z, acc[0][2]);
                acc[0][3] = fmaf(a.x, bq.w, acc[0][3]);
                acc[1][0] = fmaf(a.y, bq.x, acc[1][0]);
                acc[1][1] = fmaf(a.y, bq.y, acc[1][1]);
                acc[1][2] = fmaf(a.y, bq.z, acc[1][2]);
                acc[1][3] = fmaf(a.y, bq.w, acc[1][3]);
                acc[2][0] = fmaf(a.z, bq.x, acc[2][0]);
                acc[2][1] = fmaf(a.z, bq.y, acc[2][1]);
                acc[2][2] = fmaf(a.z, bq.z, acc[2][2]);
                acc[2][3] = fmaf(a.z, bq.w, acc[2][3]);
                acc[3][0] = fmaf(a.w, bq.x, acc[3][0]);
                acc[3][1] = fmaf(a.w, bq.y, acc[3][1]);
                acc[3][2] = fmaf(a.w, bq.z, acc[3][2]);
                acc[3][3] = fmaf(a.w, bq.w, acc[3][3]);
            }
            __syncthreads();
        }
#pragma unroll
        for (int j = 0; j < 4; j++) {
            int k = kt * 64 + tx * 4 + j;
            float c2v = g_c2[k];
#pragma unroll
            for (int i = 0; i < 4; i++) {
                float d = fmaf(-2.0f, acc[i][j], c2v);
                if (d < best[i]) { best[i] = d; besti[i] = k; }
            }
        }
    }

#pragma unroll
    for (int i = 0; i < 4; i++) {
        rv[ty * 4 + i][tx] = best[i];
        ri[ty * 4 + i][tx] = besti[i];
    }
    __syncthreads();
    if (tid < 64) {
        float bv = 3.4e38f;
        int bi = 0x7fffffff;
#pragma unroll
        for (int t = 0; t < 16; t++) {
            float v = rv[tid][t];
            int id = ri[tid][t];
            if (v < bv || (v == bv && id < bi)) { bv = v; bi = id; }
        }
        g_inds[pid[tid]] = bi;   // duplicates write identical values
    }
}

// ---------------------------------------------------------------------------
// Gather + loss (float4 codebook reads)
// ---------------------------------------------------------------------------
__global__ __launch_bounds__(256) void gather_loss(const float* __restrict__ x,
                                                   const float* __restrict__ cb,
                                                   float* __restrict__ out) {
    int t = blockIdx.x;
    int b  = t >> 6;
    int n0 = (t & 63) * 64;
    int nl = threadIdx.x & 63;
    int c0 = (threadIdx.x >> 6) * 64;

    int idx = g_inds[b * HWN + n0 + nl];
    const float4* crow = (const float4*)(cb + (size_t)idx * CDIM + c0);
    const float* xb = x   + ((size_t)b * CDIM + c0) * HWN + n0 + nl;
    float*       ob = out + ((size_t)b * CDIM + c0) * HWN + n0 + nl;

    float lsum = 0.0f;
#pragma unroll 4
    for (int i = 0; i < 16; i++) {
        float4 q = __ldg(crow + i);
        float qv[4] = {q.x, q.y, q.z, q.w};
#pragma unroll
        for (int u = 0; u < 4; u++) {
            size_t off = (size_t)(i * 4 + u) * HWN;
            float xv = xb[off];
            ob[off] = qv[u];
            float d = qv[u] - xv;
            lsum = fmaf(d, d, lsum);
        }
    }
#pragma unroll
    for (int o = 16; o; o >>= 1) lsum += __shfl_xor_sync(0xffffffffu, lsum, o);
    __shared__ float ws[8];
    if ((threadIdx.x & 31) == 0) ws[threadIdx.x >> 5] = lsum;
    __syncthreads();
    if (threadIdx.x == 0) {
        float s = 0.0f;
#pragma unroll
        for (int w = 0; w < 8; w++) s += ws[w];
        atomicAdd(&g_loss, s);
    }
}

__global__ void finalize_loss(float* __restrict__ out, int loss_off) {
    out[loss_off] = g_loss * (1.0f / (float)((size_t)BATCH * HWN * CDIM));
}

// ---------------------------------------------------------------------------
extern "C" void kernel_launch(void* const* d_in, const int* in_sizes, int n_in,
                              void* d_out, int out_size) {
    const float* x  = (const float*)d_in[0];   // [16, 256, 64, 64]
    const float* cb = (const float*)d_in[1];   // [1024, 256]
    float* out = (float*)d_out;

    cudaFuncSetAttribute(gemm_mma, cudaFuncAttributeMaxDynamicSharedMemorySize,
                         SMEM_GEMM);

    prep_transpose<<<dim3(KCODES / 32, CDIM / 32), 256>>>(cb);
    prep_c2<<<KCODES, 32>>>(cb);
    split_cb<<<KCODES * CDIM / 256, 256>>>(cb);
    split_x<<<dim3(HWN / 64, CDIM / 32, BATCH), 256>>>(x);
    gemm_mma<<<NPIX / 128, 256, SMEM_GEMM>>>();
    fixup<<<1024, 256>>>(x);
    gather_loss<<<BATCH * HWN / 64, 256>>>(x, cb, out);
    finalize_loss<<<1, 1>>>(out, out_size - 1);
}

// round 14
// speedup vs baseline: 1.4565x; 1.2168x over previous
#include <cuda_runtime.h>
#include <cuda_bf16.h>
#include <cstdint>

#define HWN    4096
#define CDIM   256
#define KCODES 1024
#define BATCH  16
#define NPIX   (BATCH * HWN)
#define MARGIN 0.012f

// ---------------------------------------------------------------------------
// Device-global scratch
// ---------------------------------------------------------------------------
__device__ __align__(16) __nv_bfloat16 g_Ah[NPIX * CDIM];     // 32 MB
__device__ __align__(16) __nv_bfloat16 g_Al[NPIX * CDIM];     // 32 MB
__device__ __align__(16) __nv_bfloat16 g_cbh[KCODES * CDIM];
__device__ __align__(16) __nv_bfloat16 g_cbl[KCODES * CDIM];
__device__ float g_ct[CDIM * KCODES];   // codebook transposed (exact fixup)
__device__ float g_c2[KCODES];
__device__ int   g_inds[NPIX];
__device__ int   g_flag[NPIX];
__device__ int   g_nflag;
__device__ float g_loss;

// ---------------------------------------------------------------------------
__device__ __forceinline__ void split2(float v, uint16_t& h, uint16_t& l) {
    __nv_bfloat16 bh = __float2bfloat16_rn(v);
    __nv_bfloat16 bl = __float2bfloat16_rn(v - __bfloat162float(bh));
    h = __bfloat16_as_ushort(bh);
    l = __bfloat16_as_ushort(bl);
}

__device__ __forceinline__ uint32_t smem_u32(const void* p) {
    uint32_t a;
    asm("{ .reg .u64 t; cvta.to.shared.u64 t, %1; cvt.u32.u64 %0, t; }" : "=r"(a) : "l"(p));
    return a;
}
__device__ __forceinline__ void cp16(uint32_t dst, const void* src) {
    asm volatile("cp.async.cg.shared.global [%0], [%1], 16;" :: "r"(dst), "l"(src) : "memory");
}
#define CP_COMMIT() asm volatile("cp.async.commit_group;" ::: "memory")
#define CP_WAIT1()  asm volatile("cp.async.wait_group 1;" ::: "memory")
#define CP_WAIT0()  asm volatile("cp.async.wait_group 0;" ::: "memory")

__device__ __forceinline__ void ldsm4(uint32_t* r, uint32_t addr) {
    asm volatile("ldmatrix.sync.aligned.m8n8.x4.shared.b16 {%0,%1,%2,%3}, [%4];"
                 : "=r"(r[0]), "=r"(r[1]), "=r"(r[2]), "=r"(r[3]) : "r"(addr));
}
__device__ __forceinline__ void mma16816(float* d, const uint32_t* a,
                                         const uint32_t* b) {
    asm volatile(
        "mma.sync.aligned.m16n8k16.row.col.f32.bf16.bf16.f32 "
        "{%0,%1,%2,%3}, {%4,%5,%6,%7}, {%8,%9}, {%0,%1,%2,%3};"
        : "+f"(d[0]), "+f"(d[1]), "+f"(d[2]), "+f"(d[3])
        : "r"(a[0]), "r"(a[1]), "r"(a[2]), "r"(a[3]), "r"(b[0]), "r"(b[1]));
}

// ---------------------------------------------------------------------------
// Prep kernels
// ---------------------------------------------------------------------------
__global__ void prep_transpose(const float* __restrict__ cb) {
    __shared__ float tile[32][33];
    int k0 = blockIdx.x * 32, c0 = blockIdx.y * 32;
    int tx = threadIdx.x & 31, r0 = threadIdx.x >> 5;
#pragma unroll
    for (int i = 0; i < 4; i++)
        tile[r0 + i * 8][tx] = cb[(size_t)(k0 + r0 + i * 8) * CDIM + c0 + tx];
    __syncthreads();
#pragma unroll
    for (int i = 0; i < 4; i++)
        g_ct[(size_t)(c0 + r0 + i * 8) * KCODES + k0 + tx] = tile[tx][r0 + i * 8];
    if (blockIdx.x == 0 && blockIdx.y == 0 && threadIdx.x == 0) {
        g_loss = 0.0f;
        g_nflag = 0;
    }
}

__global__ void prep_c2(const float* __restrict__ cb) {
    int k = blockIdx.x, lane = threadIdx.x;
    float s = 0.0f;
#pragma unroll
    for (int c = lane; c < CDIM; c += 32) {
        float v = cb[(size_t)k * CDIM + c];
        s += v * v;
    }
#pragma unroll
    for (int o = 16; o; o >>= 1) s += __shfl_xor_sync(0xffffffffu, s, o);
    if (lane == 0) g_c2[k] = s;
}

__global__ __launch_bounds__(256) void split_cb(const float* __restrict__ cb) {
    int i = blockIdx.x * 256 + threadIdx.x;
    float v = cb[i];
    uint16_t h, l;
    split2(v, h, l);
    g_cbh[i] = __ushort_as_bfloat16(h);
    g_cbl[i] = __ushort_as_bfloat16(l);
}

__global__ __launch_bounds__(256) void split_x(const float* __restrict__ x) {
    __shared__ float tile[64][33];
    int n0 = blockIdx.x * 64, c0 = blockIdx.y * 32, b = blockIdx.z;
    int tid = threadIdx.x;
    int nn = tid & 63, cb_ = tid >> 6;
#pragma unroll
    for (int i = 0; i < 8; i++) {
        int cl = cb_ + i * 4;
        tile[nn][cl] = x[(size_t)(b * CDIM + c0 + cl) * HWN + n0 + nn];
    }
    __syncthreads();
    int pl = tid >> 2, quad = tid & 3;
    size_t base = (size_t)(b * HWN + n0 + pl) * CDIM + c0 + quad * 8;
    uint32_t hw[4], lw[4];
#pragma unroll
    for (int u = 0; u < 4; u++) {
        uint16_t h0, l0, h1, l1;
        split2(tile[pl][quad * 8 + u * 2 + 0], h0, l0);
        split2(tile[pl][quad * 8 + u * 2 + 1], h1, l1);
        hw[u] = (uint32_t)h0 | ((uint32_t)h1 << 16);
        lw[u] = (uint32_t)l0 | ((uint32_t)l1 << 16);
    }
    *(uint4*)(g_Ah + base) = make_uint4(hw[0], hw[1], hw[2], hw[3]);
    *(uint4*)(g_Al + base) = make_uint4(lw[0], lw[1], lw[2], lw[3]);
}

// ---------------------------------------------------------------------------
// Tensor-core approximate GEMM + top-2 argmin + flagging.
// CTA: 128 pixels x 1024 codes, 8 warps (2M x 4N), warp tile 64x32.
// ldmatrix fragment loads; Ah/Bh fragments reused across the 3 products;
// B chunks (128 codes x 64 ch x 2 splits) double-buffered via cp.async.
// ---------------------------------------------------------------------------
#define APITCH 528
#define BPITCH 144
#define OFF_AH 0
#define OFF_AL 67584
#define OFF_B  135168            // [buf][split]: buf stride 36864, split 18432
#define OFF_C2 208896
#define OFF_RB 212992
#define OFF_RS 215040
#define OFF_RI 217088
#define SMEM_GEMM 219136

__global__ __launch_bounds__(256, 1) void gemm_mma(void) {
    extern __shared__ __align__(16) unsigned char smem[];
    const uint32_t smb = smem_u32(smem);
    const int tid = threadIdx.x;
    const int wid = tid >> 5, lane = tid & 31;
    const int g = lane >> 2, tig = lane & 3;
    const int warpM = wid & 1, warpN = wid >> 1;
    const int laneR = lane & 15, laneK = (lane >> 4) << 3;

    // ---- stage A (both splits) resident: 128 px x 256 ch ----
    {
        const __nv_bfloat16* srcs[2] = {g_Ah, g_Al};
        const int offs[2] = {OFF_AH, OFF_AL};
#pragma unroll
        for (int s = 0; s < 2; s++) {
            const uint4* src = (const uint4*)(srcs[s] + (size_t)blockIdx.x * 128 * CDIM);
#pragma unroll
            for (int i = 0; i < 16; i++) {
                int idx = tid + i * 256;
                int r = idx >> 5, c16 = idx & 31;
                *(uint4*)(smem + offs[s] + r * APITCH + c16 * 16) = src[idx];
            }
        }
#pragma unroll
        for (int i = 0; i < 4; i++)
            ((float*)(smem + OFF_C2))[tid + i * 256] = g_c2[tid + i * 256];
    }

    // ---- prologue: issue B chunk 0 ----
    {
#pragma unroll
        for (int s = 0; s < 2; s++) {
            const uint4* src = (const uint4*)(s ? g_cbl : g_cbh);
            uint32_t db = smb + OFF_B + s * 18432;
#pragma unroll
            for (int i = 0; i < 4; i++) {
                int idx = tid + i * 256;
                int r = idx >> 3, q = idx & 7;
                cp16(db + r * BPITCH + q * 16, src + r * 32 + q);
            }
        }
        CP_COMMIT();
    }

    float bestv[8], secv[8];
    int bidx[8];
#pragma unroll
    for (int r = 0; r < 8; r++) { bestv[r] = 3.4e38f; secv[r] = 3.4e38f; bidx[r] = 0; }
    const float* c2s = (const float*)(smem + OFF_C2);

    float acc[4][4][4];

    // per-thread ldmatrix base addresses
    const uint32_t aAddr = smb + (warpM * 64 + laneR) * APITCH + laneK * 2;
    const uint32_t bAddr = smb + OFF_B + (warpN * 32 + laneR) * BPITCH + laneK * 2;

#pragma unroll 1
    for (int ci = 0; ci < 32; ci++) {
        const int nt = ci >> 2, kc = ci & 3, buf = ci & 1;
        // issue next chunk into other buffer
        if (ci < 31) {
            const int nnt = (ci + 1) >> 2, nkc = (ci + 1) & 3;
            const uint32_t dbase = smb + OFF_B + ((ci + 1) & 1) * 36864;
#pragma unroll
            for (int s = 0; s < 2; s++) {
                const uint4* src = (const uint4*)(s ? g_cbl : g_cbh);
                uint32_t db = dbase + s * 18432;
#pragma unroll
                for (int i = 0; i < 4; i++) {
                    int idx = tid + i * 256;
                    int r = idx >> 3, q = idx & 7;
                    cp16(db + r * BPITCH + q * 16,
                         src + (nnt * 128 + r) * 32 + nkc * 8 + q);
                }
            }
            CP_COMMIT();
            CP_WAIT1();
        } else {
            CP_WAIT0();
        }
        __syncthreads();

        if (kc == 0) {
#pragma unroll
            for (int mi = 0; mi < 4; mi++)
#pragma unroll
                for (int ni = 0; ni < 4; ni++)
#pragma unroll
                    for (int e = 0; e < 4; e++) acc[mi][ni][e] = 0.0f;
        }

        const uint32_t bBufH = bAddr + buf * 36864;
        const uint32_t bBufL = bBufH + 18432;
#pragma unroll
        for (int ks = 0; ks < 4; ks++) {
            const uint32_t akOff = (uint32_t)(kc * 64 + ks * 16) * 2;
            uint32_t ah[4][4], al[4][4];
#pragma unroll
            for (int mi = 0; mi < 4; mi++) {
                uint32_t ao = aAddr + mi * (16 * APITCH) + akOff;
                ldsm4(ah[mi], ao + OFF_AH);
                ldsm4(al[mi], ao + OFF_AL);
            }
            uint32_t bh[4][2], bl[4][2];
#pragma unroll
            for (int np = 0; np < 2; np++) {
                uint32_t bo = np * (16 * BPITCH) + (uint32_t)(ks * 16) * 2;
                uint32_t r4[4];
                ldsm4(r4, bBufH + bo);
                bh[np * 2][0] = r4[0]; bh[np * 2 + 1][0] = r4[1];
                bh[np * 2][1] = r4[2]; bh[np * 2 + 1][1] = r4[3];
                ldsm4(r4, bBufL + bo);
                bl[np * 2][0] = r4[0]; bl[np * 2 + 1][0] = r4[1];
                bl[np * 2][1] = r4[2]; bl[np * 2 + 1][1] = r4[3];
            }
#pragma unroll
            for (int mi = 0; mi < 4; mi++)
#pragma unroll
                for (int ni = 0; ni < 4; ni++)
                    mma16816(acc[mi][ni], ah[mi], bh[ni]);
#pragma unroll
            for (int mi = 0; mi < 4; mi++)
#pragma unroll
                for (int ni = 0; ni < 4; ni++)
                    mma16816(acc[mi][ni], ah[mi], bl[ni]);
#pragma unroll
            for (int mi = 0; mi < 4; mi++)
#pragma unroll
                for (int ni = 0; ni < 4; ni++)
                    mma16816(acc[mi][ni], al[mi], bh[ni]);
        }

        if (kc == 3) {
            // fold into per-lane top-2 (ascending code order within lane)
#pragma unroll
            for (int ni = 0; ni < 4; ni++) {
                int cg = nt * 128 + warpN * 32 + ni * 8 + tig * 2;
                float c20 = c2s[cg], c21 = c2s[cg + 1];
#pragma unroll
                for (int mi = 0; mi < 4; mi++) {
#pragma unroll
                    for (int e = 0; e < 4; e++) {
                        int r8 = mi * 2 + (e >> 1);
                        float v = fmaf(-2.0f, acc[mi][ni][e], (e & 1) ? c21 : c20);
                        int k = cg + (e & 1);
                        if (v < bestv[r8]) {
                            secv[r8] = bestv[r8];
                            bestv[r8] = v;
                            bidx[r8] = k;
                        } else if (v < secv[r8]) {
                            secv[r8] = v;
                        }
                    }
                }
            }
        }
        if (ci < 31) __syncthreads();
    }

    // ---- quad merge (lanes sharing rows) ----
#pragma unroll
    for (int o = 1; o <= 2; o <<= 1) {
#pragma unroll
        for (int r = 0; r < 8; r++) {
            float ob = __shfl_xor_sync(0xffffffffu, bestv[r], o);
            float os = __shfl_xor_sync(0xffffffffu, secv[r], o);
            int oi = __shfl_xor_sync(0xffffffffu, bidx[r], o);
            bool take = (ob < bestv[r]) || (ob == bestv[r] && oi < bidx[r]);
            float loser = take ? bestv[r] : ob;
            if (take) { bestv[r] = ob; bidx[r] = oi; }
            secv[r] = fminf(fminf(secv[r], os), loser);
        }
    }

    float* redb = (float*)(smem + OFF_RB);
    float* reds = (float*)(smem + OFF_RS);
    int*   redi = (int*)(smem + OFF_RI);
    if (tig == 0) {
#pragma unroll
        for (int r8 = 0; r8 < 8; r8++) {
            int row = warpM * 64 + (r8 >> 1) * 16 + (r8 & 1) * 8 + g;
            redb[warpN * 128 + row] = bestv[r8];
            reds[warpN * 128 + row] = secv[r8];
            redi[warpN * 128 + row] = bidx[r8];
        }
    }
    __syncthreads();

    if (tid < 128) {
        float bv = 3.4e38f, sv = 3.4e38f;
        int bi = 0x7fffffff;
#pragma unroll
        for (int w = 0; w < 4; w++) {
            float ob = redb[w * 128 + tid];
            float os = reds[w * 128 + tid];
            int oi = redi[w * 128 + tid];
            bool take = (ob < bv) || (ob == bv && oi < bi);
            float loser = take ? bv : ob;
            if (take) { bv = ob; bi = oi; }
            sv = fminf(fminf(sv, os), loser);
        }
        int pixel = blockIdx.x * 128 + tid;
        g_inds[pixel] = bi;
        if (sv - bv < MARGIN) {
            int slot = atomicAdd(&g_nflag, 1);
            g_flag[slot] = pixel;
        }
    }
}

// ---------------------------------------------------------------------------
// Exact fp32 fixup: 16 flagged pixels per block x all 1024 codes.
// ---------------------------------------------------------------------------
__global__ __launch_bounds__(256) void fixup(const float* __restrict__ x) {
    int nflag = g_nflag;
    int base = blockIdx.x * 16;
    if (base >= nflag) return;

    __shared__ float As[32][17];
    __shared__ float Bs[32][64];
    __shared__ float rv[16][17];
    __shared__ int   ri[16][17];
    __shared__ int   pid[16];
    __shared__ size_t pbase[16];

    const int tid = threadIdx.x;
    if (tid < 16) {
        int src = base + tid;
        if (src >= nflag) src = base;
        int p = g_flag[src];
        pid[tid] = p;
        pbase[tid] = (size_t)(p >> 12) * CDIM * HWN + (p & 4095);
    }
    __syncthreads();

    const int tx = tid & 15, ty = tid >> 4;
    float best = 3.4e38f;
    int besti = 0;

    for (int kt = 0; kt < 16; kt++) {
        float acc[4] = {0.0f, 0.0f, 0.0f, 0.0f};
#pragma unroll 1
        for (int cc = 0; cc < CDIM; cc += 32) {
            // As: 512 entries, 2 per thread
#pragma unroll
            for (int i = 0; i < 2; i++) {
                int idx = tid + i * 256;
                int r = idx >> 4, px = idx & 15;
                As[r][px] = x[pbase[px] + (size_t)(cc + r) * HWN];
            }
            // Bs: 2048 entries, 8 per thread, coalesced
#pragma unroll
            for (int i = 0; i < 8; i++) {
                int idx = tid + i * 256;
                int r = idx >> 6, col = idx & 63;
                Bs[r][col] = g_ct[(size_t)(cc + r) * KCODES + kt * 64 + col];
            }
            __syncthreads();
#pragma unroll
            for (int c = 0; c < 32; c++) {
                float a = As[c][ty];
                float4 b4 = *(const float4*)&Bs[c][tx * 4];
                acc[0] = fmaf(a, b4.x, acc[0]);
                acc[1] = fmaf(a, b4.y, acc[1]);
                acc[2] = fmaf(a, b4.z, acc[2]);
                acc[3] = fmaf(a, b4.w, acc[3]);
            }
            __syncthreads();
        }
#pragma unroll
        for (int j = 0; j < 4; j++) {
            int k = kt * 64 + tx * 4 + j;
            float d = fmaf(-2.0f, acc[j], g_c2[k]);
            if (d < best) { best = d; besti = k; }
        }
    }

    rv[ty][tx] = best;
    ri[ty][tx] = besti;
    __syncthreads();
    if (tid < 16) {
        float bv = 3.4e38f;
        int bi = 0x7fffffff;
#pragma unroll
        for (int t = 0; t < 16; t++) {
            float v = rv[tid][t];
            int id = ri[tid][t];
            if (v < bv || (v == bv && id < bi)) { bv = v; bi = id; }
        }
        g_inds[pid[tid]] = bi;   // duplicate pixels write identical values
    }
}

// ---------------------------------------------------------------------------
// Gather + loss
// ---------------------------------------------------------------------------
__global__ __launch_bounds__(256) void gather_loss(const float* __restrict__ x,
                                                   const float* __restrict__ cb,
                                                   float* __restrict__ out) {
    int t = blockIdx.x;
    int b  = t >> 6;
    int n0 = (t & 63) * 64;
    int nl = threadIdx.x & 63;
    int c0 = (threadIdx.x >> 6) * 64;

    int idx = g_inds[b * HWN + n0 + nl];
    const float4* crow = (const float4*)(cb + (size_t)idx * CDIM + c0);
    const float* xb = x   + ((size_t)b * CDIM + c0) * HWN + n0 + nl;
    float*       ob = out + ((size_t)b * CDIM + c0) * HWN + n0 + nl;

    float lsum = 0.0f;
#pragma unroll 4
    for (int i = 0; i < 16; i++) {
        float4 q = __ldg(crow + i);
        float qv[4] = {q.x, q.y, q.z, q.w};
#pragma unroll
        for (int u = 0; u < 4; u++) {
            size_t off = (size_t)(i * 4 + u) * HWN;
            float xv = xb[off];
            ob[off] = qv[u];
            float d = qv[u] - xv;
            lsum = fmaf(d, d, lsum);
        }
    }
#pragma unroll
    for (int o = 16; o; o >>= 1) lsum += __shfl_xor_sync(0xffffffffu, lsum, o);
    __shared__ float ws[8];
    if ((threadIdx.x & 31) == 0) ws[threadIdx.x >> 5] = lsum;
    __syncthreads();
    if (threadIdx.x == 0) {
        float s = 0.0f;
#pragma unroll
        for (int w = 0; w < 8; w++) s += ws[w];
        atomicAdd(&g_loss, s);
    }
}

__global__ void finalize_loss(float* __restrict__ out, int loss_off) {
    out[loss_off] = g_loss * (1.0f / (float)((size_t)BATCH * HWN * CDIM));
}

// ---------------------------------------------------------------------------
extern "C" void kernel_launch(void* const* d_in, const int* in_sizes, int n_in,
                              void* d_out, int out_size) {
    const float* x  = (const float*)d_in[0];   // [16, 256, 64, 64]
    const float* cb = (const float*)d_in[1];   // [1024, 256]
    float* out = (float*)d_out;

    cudaFuncSetAttribute(gemm_mma, cudaFuncAttributeMaxDynamicSharedMemorySize,
                         SMEM_GEMM);

    prep_transpose<<<dim3(KCODES / 32, CDIM / 32), 256>>>(cb);
    prep_c2<<<KCODES, 32>>>(cb);
    split_cb<<<KCODES * CDIM / 256, 256>>>(cb);
    split_x<<<dim3(HWN / 64, CDIM / 32, BATCH), 256>>>(x);
    gemm_mma<<<NPIX / 128, 256, SMEM_GEMM>>>();
    fixup<<<NPIX / 16, 256>>>(x);
    gather_loss<<<BATCH * HWN / 64, 256>>>(x, cb, out);
    finalize_loss<<<1, 1>>>(out, out_size - 1);
}

// round 15
// speedup vs baseline: 1.5273x; 1.0486x over previous
#include <cuda_runtime.h>
#include <cuda_bf16.h>
#include <cstdint>

#define HWN    4096
#define CDIM   256
#define KCODES 1024
#define BATCH  16
#define NPIX   (BATCH * HWN)
#define MARGIN 0.012f

// ---------------------------------------------------------------------------
// Device-global scratch
// ---------------------------------------------------------------------------
__device__ __align__(16) __nv_bfloat16 g_cbh[KCODES * CDIM];
__device__ __align__(16) __nv_bfloat16 g_cbl[KCODES * CDIM];
__device__ float g_ct[CDIM * KCODES];   // codebook transposed (exact fixup)
__device__ float g_c2[KCODES];
__device__ int   g_inds[NPIX];
__device__ int   g_flag[NPIX];
__device__ int   g_nflag;
__device__ float g_loss;

// ---------------------------------------------------------------------------
__device__ __forceinline__ void split2(float v, uint16_t& h, uint16_t& l) {
    __nv_bfloat16 bh = __float2bfloat16_rn(v);
    __nv_bfloat16 bl = __float2bfloat16_rn(v - __bfloat162float(bh));
    h = __bfloat16_as_ushort(bh);
    l = __bfloat16_as_ushort(bl);
}

__device__ __forceinline__ uint32_t smem_u32(const void* p) {
    uint32_t a;
    asm("{ .reg .u64 t; cvta.to.shared.u64 t, %1; cvt.u32.u64 %0, t; }" : "=r"(a) : "l"(p));
    return a;
}
__device__ __forceinline__ void cp16(uint32_t dst, const void* src) {
    asm volatile("cp.async.cg.shared.global [%0], [%1], 16;" :: "r"(dst), "l"(src) : "memory");
}
#define CP_COMMIT() asm volatile("cp.async.commit_group;" ::: "memory")
#define CP_WAIT1()  asm volatile("cp.async.wait_group 1;" ::: "memory")
#define CP_WAIT0()  asm volatile("cp.async.wait_group 0;" ::: "memory")

__device__ __forceinline__ void ldsm4(uint32_t* r, uint32_t addr) {
    asm volatile("ldmatrix.sync.aligned.m8n8.x4.shared.b16 {%0,%1,%2,%3}, [%4];"
                 : "=r"(r[0]), "=r"(r[1]), "=r"(r[2]), "=r"(r[3]) : "r"(addr));
}
__device__ __forceinline__ void mma16816(float* d, const uint32_t* a,
                                         const uint32_t* b) {
    asm volatile(
        "mma.sync.aligned.m16n8k16.row.col.f32.bf16.bf16.f32 "
        "{%0,%1,%2,%3}, {%4,%5,%6,%7}, {%8,%9}, {%0,%1,%2,%3};"
        : "+f"(d[0]), "+f"(d[1]), "+f"(d[2]), "+f"(d[3])
        : "r"(a[0]), "r"(a[1]), "r"(a[2]), "r"(a[3]), "r"(b[0]), "r"(b[1]));
}

// ---------------------------------------------------------------------------
// Prep kernels
// ---------------------------------------------------------------------------
__global__ void prep_transpose(const float* __restrict__ cb) {
    __shared__ float tile[32][33];
    int k0 = blockIdx.x * 32, c0 = blockIdx.y * 32;
    int tx = threadIdx.x & 31, r0 = threadIdx.x >> 5;
#pragma unroll
    for (int i = 0; i < 4; i++)
        tile[r0 + i * 8][tx] = cb[(size_t)(k0 + r0 + i * 8) * CDIM + c0 + tx];
    __syncthreads();
#pragma unroll
    for (int i = 0; i < 4; i++)
        g_ct[(size_t)(c0 + r0 + i * 8) * KCODES + k0 + tx] = tile[tx][r0 + i * 8];
    if (blockIdx.x == 0 && blockIdx.y == 0 && threadIdx.x == 0) {
        g_loss = 0.0f;
        g_nflag = 0;
    }
}

__global__ void prep_c2(const float* __restrict__ cb) {
    int k = blockIdx.x, lane = threadIdx.x;
    float s = 0.0f;
#pragma unroll
    for (int c = lane; c < CDIM; c += 32) {
        float v = cb[(size_t)k * CDIM + c];
        s += v * v;
    }
#pragma unroll
    for (int o = 16; o; o >>= 1) s += __shfl_xor_sync(0xffffffffu, s, o);
    if (lane == 0) g_c2[k] = s;
}

__global__ __launch_bounds__(256) void split_cb(const float* __restrict__ cb) {
    int i = blockIdx.x * 256 + threadIdx.x;
    float v = cb[i];
    uint16_t h, l;
    split2(v, h, l);
    g_cbh[i] = __ushort_as_bfloat16(h);
    g_cbl[i] = __ushort_as_bfloat16(l);
}

// ---------------------------------------------------------------------------
// Tensor-core approximate GEMM + top-2 argmin + flagging.
// CTA: 64 pixels x 1024 codes, 8 warps, warp tile 64px x 16 codes.
// A split fused in-prologue from fp32 x. B chunks (128 codes x 64 ch x 2
// splits) 3-stage cp.async pipeline, single sync per chunk.
// ---------------------------------------------------------------------------
#define APITCH 528
#define BPITCH 144
#define OFF_AH 0
#define OFF_AL 33792
#define OFF_B  67584
#define BUFSZ  36864
#define SPLSZ  18432
#define OFF_C2 178176
#define OFF_RB 182272
#define OFF_RS 184320
#define OFF_RI 186368
#define SMEM_GEMM 188416

__global__ __launch_bounds__(256, 1) void gemm_mma(const float* __restrict__ x) {
    extern __shared__ __align__(16) unsigned char smem[];
    const uint32_t smb = smem_u32(smem);
    const int tid = threadIdx.x;
    const int wid = tid >> 5, lane = tid & 31;
    const int g = lane >> 2, tig = lane & 3;
    const int warpN = wid;                    // 16 codes per warp per n-tile
    const int laneR = lane & 15, laneK = (lane >> 4) << 3;

    auto issueB = [&](int ch, int buf) {
        const int nt = ch >> 2, kc = ch & 3;
        const uint32_t dbase = smb + OFF_B + buf * BUFSZ;
#pragma unroll
        for (int s = 0; s < 2; s++) {
            const uint4* src = (const uint4*)(s ? g_cbl : g_cbh);
            uint32_t db = dbase + s * SPLSZ;
#pragma unroll
            for (int i = 0; i < 4; i++) {
                int idx = tid + i * 256;
                int r = idx >> 3, q = idx & 7;
                cp16(db + r * BPITCH + q * 16, src + (nt * 128 + r) * 32 + kc * 8 + q);
            }
        }
        CP_COMMIT();
    };

    // ---- pipeline prologue: chunks 0,1 in flight ----
    issueB(0, 0);
    issueB(1, 1);

    // ---- fused A load + split (overlaps with cp.async) ----
    {
        const int b = blockIdx.x >> 6;
        const int n0 = (blockIdx.x & 63) * 64;
        const int px = tid & 63, cg4 = tid >> 6;
        const float* xb = x + (size_t)b * CDIM * HWN + n0 + px;
        unsigned char* ahb = smem + OFF_AH + px * APITCH;
        unsigned char* alb = smem + OFF_AL + px * APITCH;
#pragma unroll 8
        for (int i = 0; i < 64; i++) {
            int c = cg4 * 64 + i;
            float v = __ldg(xb + (size_t)c * HWN);
            uint16_t h, l;
            split2(v, h, l);
            *(uint16_t*)(ahb + c * 2) = h;
            *(uint16_t*)(alb + c * 2) = l;
        }
#pragma unroll
        for (int i = 0; i < 4; i++)
            ((float*)(smem + OFF_C2))[tid + i * 256] = g_c2[tid + i * 256];
    }

    float bestv[8], secv[8];
    int bidx[8];
#pragma unroll
    for (int r = 0; r < 8; r++) { bestv[r] = 3.4e38f; secv[r] = 3.4e38f; bidx[r] = 0; }
    const float* c2s = (const float*)(smem + OFF_C2);

    float acc[4][2][4];
    const uint32_t aAddrH = smb + OFF_AH + laneR * APITCH + laneK * 2;
    const uint32_t aAddrL = smb + OFF_AL + laneR * APITCH + laneK * 2;
    const uint32_t bAddr  = smb + OFF_B + (warpN * 16 + laneR) * BPITCH + laneK * 2;

#pragma unroll 1
    for (int ci = 0; ci < 32; ci++) {
        const int nt = ci >> 2, kc = ci & 3, buf = ci % 3;
        if (ci == 31) { CP_WAIT0(); } else { CP_WAIT1(); }
        __syncthreads();   // publishes chunk ci; guards buf (ci+2)%3 reuse

        if (kc == 0) {
#pragma unroll
            for (int mi = 0; mi < 4; mi++)
#pragma unroll
                for (int ni = 0; ni < 2; ni++)
#pragma unroll
                    for (int e = 0; e < 4; e++) acc[mi][ni][e] = 0.0f;
        }

        const uint32_t bH = bAddr + buf * BUFSZ;
        const uint32_t bL = bH + SPLSZ;
#pragma unroll
        for (int ks = 0; ks < 4; ks++) {
            const uint32_t ak = (uint32_t)(kc * 64 + ks * 16) * 2;
            uint32_t ah[4][4], al[4][4];
#pragma unroll
            for (int mi = 0; mi < 4; mi++) {
                ldsm4(ah[mi], aAddrH + mi * (16 * APITCH) + ak);
                ldsm4(al[mi], aAddrL + mi * (16 * APITCH) + ak);
            }
            uint32_t bh[2][2], bl[2][2], r4[4];
            ldsm4(r4, bH + ks * 32);
            bh[0][0] = r4[0]; bh[1][0] = r4[1]; bh[0][1] = r4[2]; bh[1][1] = r4[3];
            ldsm4(r4, bL + ks * 32);
            bl[0][0] = r4[0]; bl[1][0] = r4[1]; bl[0][1] = r4[2]; bl[1][1] = r4[3];

#pragma unroll
            for (int mi = 0; mi < 4; mi++)
#pragma unroll
                for (int ni = 0; ni < 2; ni++)
                    mma16816(acc[mi][ni], ah[mi], bh[ni]);
#pragma unroll
            for (int mi = 0; mi < 4; mi++)
#pragma unroll
                for (int ni = 0; ni < 2; ni++)
                    mma16816(acc[mi][ni], ah[mi], bl[ni]);
#pragma unroll
            for (int mi = 0; mi < 4; mi++)
#pragma unroll
                for (int ni = 0; ni < 2; ni++)
                    mma16816(acc[mi][ni], al[mi], bh[ni]);
        }

        if (kc == 3) {
            // fold into per-lane top-2 (ascending code order per row slot)
#pragma unroll
            for (int ni = 0; ni < 2; ni++) {
                int cg = nt * 128 + warpN * 16 + ni * 8 + tig * 2;
                float c20 = c2s[cg], c21 = c2s[cg + 1];
#pragma unroll
                for (int mi = 0; mi < 4; mi++) {
#pragma unroll
                    for (int e = 0; e < 4; e++) {
                        int r8 = mi * 2 + (e >> 1);
                        float v = fmaf(-2.0f, acc[mi][ni][e], (e & 1) ? c21 : c20);
                        int k = cg + (e & 1);
                        if (v < bestv[r8]) {
                            secv[r8] = bestv[r8];
                            bestv[r8] = v;
                            bidx[r8] = k;
                        } else if (v < secv[r8]) {
                            secv[r8] = v;
                        }
                    }
                }
            }
        }

        if (ci < 30) issueB(ci + 2, (ci + 2) % 3);
    }

    // ---- quad merge (lanes with same g share rows) ----
#pragma unroll
    for (int o = 1; o <= 2; o <<= 1) {
#pragma unroll
        for (int r = 0; r < 8; r++) {
            float ob = __shfl_xor_sync(0xffffffffu, bestv[r], o);
            float os = __shfl_xor_sync(0xffffffffu, secv[r], o);
            int oi = __shfl_xor_sync(0xffffffffu, bidx[r], o);
            bool take = (ob < bestv[r]) || (ob == bestv[r] && oi < bidx[r]);
            float loser = take ? bestv[r] : ob;
            if (take) { bestv[r] = ob; bidx[r] = oi; }
            secv[r] = fminf(fminf(secv[r], os), loser);
        }
    }

    float* redb = (float*)(smem + OFF_RB);
    float* reds = (float*)(smem + OFF_RS);
    int*   redi = (int*)(smem + OFF_RI);
    if (tig == 0) {
#pragma unroll
        for (int r8 = 0; r8 < 8; r8++) {
            int row = (r8 >> 1) * 16 + (r8 & 1) * 8 + g;    // 0..63
            redb[warpN * 64 + row] = bestv[r8];
            reds[warpN * 64 + row] = secv[r8];
            redi[warpN * 64 + row] = bidx[r8];
        }
    }
    __syncthreads();

    if (tid < 64) {
        float bv = 3.4e38f, sv = 3.4e38f;
        int bi = 0x7fffffff;
#pragma unroll
        for (int w = 0; w < 8; w++) {
            float ob = redb[w * 64 + tid];
            float os = reds[w * 64 + tid];
            int oi = redi[w * 64 + tid];
            bool take = (ob < bv) || (ob == bv && oi < bi);
            float loser = take ? bv : ob;
            if (take) { bv = ob; bi = oi; }
            sv = fminf(fminf(sv, os), loser);
        }
        int pixel = blockIdx.x * 64 + tid;
        g_inds[pixel] = bi;
        if (sv - bv < MARGIN) {
            int slot = atomicAdd(&g_nflag, 1);
            g_flag[slot] = pixel;
        }
    }
}

// ---------------------------------------------------------------------------
// Exact fp32 fixup: 16 flagged pixels per block x all 1024 codes.
// ---------------------------------------------------------------------------
__global__ __launch_bounds__(256) void fixup(const float* __restrict__ x) {
    int nflag = g_nflag;
    int base = blockIdx.x * 16;
    if (base >= nflag) return;

    __shared__ float As[32][17];
    __shared__ float Bs[32][64];
    __shared__ float rv[16][17];
    __shared__ int   ri[16][17];
    __shared__ int   pid[16];
    __shared__ size_t pbase[16];

    const int tid = threadIdx.x;
    if (tid < 16) {
        int src = base + tid;
        if (src >= nflag) src = base;
        int p = g_flag[src];
        pid[tid] = p;
        pbase[tid] = (size_t)(p >> 12) * CDIM * HWN + (p & 4095);
    }
    __syncthreads();

    const int tx = tid & 15, ty = tid >> 4;
    float best = 3.4e38f;
    int besti = 0;

    for (int kt = 0; kt < 16; kt++) {
        float acc[4] = {0.0f, 0.0f, 0.0f, 0.0f};
#pragma unroll 1
        for (int cc = 0; cc < CDIM; cc += 32) {
#pragma unroll
            for (int i = 0; i < 2; i++) {
                int idx = tid + i * 256;
                int r = idx >> 4, px = idx & 15;
                As[r][px] = x[pbase[px] + (size_t)(cc + r) * HWN];
            }
#pragma unroll
            for (int i = 0; i < 8; i++) {
                int idx = tid + i * 256;
                int r = idx >> 6, col = idx & 63;
                Bs[r][col] = g_ct[(size_t)(cc + r) * KCODES + kt * 64 + col];
            }
            __syncthreads();
#pragma unroll
            for (int c = 0; c < 32; c++) {
                float a = As[c][ty];
                float4 b4 = *(const float4*)&Bs[c][tx * 4];
                acc[0] = fmaf(a, b4.x, acc[0]);
                acc[1] = fmaf(a, b4.y, acc[1]);
                acc[2] = fmaf(a, b4.z, acc[2]);
                acc[3] = fmaf(a, b4.w, acc[3]);
            }
            __syncthreads();
        }
#pragma unroll
        for (int j = 0; j < 4; j++) {
            int k = kt * 64 + tx * 4 + j;
            float d = fmaf(-2.0f, acc[j], g_c2[k]);
            if (d < best) { best = d; besti = k; }
        }
    }

    rv[ty][tx] = best;
    ri[ty][tx] = besti;
    __syncthreads();
    if (tid < 16) {
        float bv = 3.4e38f;
        int bi = 0x7fffffff;
#pragma unroll
        for (int t = 0; t < 16; t++) {
            float v = rv[tid][t];
            int id = ri[tid][t];
            if (v < bv || (v == bv && id < bi)) { bv = v; bi = id; }
        }
        g_inds[pid[tid]] = bi;   // duplicate pixels write identical values
    }
}

// ---------------------------------------------------------------------------
// Gather + loss
// ---------------------------------------------------------------------------
__global__ __launch_bounds__(256) void gather_loss(const float* __restrict__ x,
                                                   const float* __restrict__ cb,
                                                   float* __restrict__ out) {
    int t = blockIdx.x;
    int b  = t >> 6;
    int n0 = (t & 63) * 64;
    int nl = threadIdx.x & 63;
    int c0 = (threadIdx.x >> 6) * 64;

    int idx = g_inds[b * HWN + n0 + nl];
    const float4* crow = (const float4*)(cb + (size_t)idx * CDIM + c0);
    const float* xb = x   + ((size_t)b * CDIM + c0) * HWN + n0 + nl;
    float*       ob = out + ((size_t)b * CDIM + c0) * HWN + n0 + nl;

    float lsum = 0.0f;
#pragma unroll 4
    for (int i = 0; i < 16; i++) {
        float4 q = __ldg(crow + i);
        float qv[4] = {q.x, q.y, q.z, q.w};
#pragma unroll
        for (int u = 0; u < 4; u++) {
            size_t off = (size_t)(i * 4 + u) * HWN;
            float xv = xb[off];
            ob[off] = qv[u];
            float d = qv[u] - xv;
            lsum = fmaf(d, d, lsum);
        }
    }
#pragma unroll
    for (int o = 16; o; o >>= 1) lsum += __shfl_xor_sync(0xffffffffu, lsum, o);
    __shared__ float ws[8];
    if ((threadIdx.x & 31) == 0) ws[threadIdx.x >> 5] = lsum;
    __syncthreads();
    if (threadIdx.x == 0) {
        float s = 0.0f;
#pragma unroll
        for (int w = 0; w < 8; w++) s += ws[w];
        atomicAdd(&g_loss, s);
    }
}

__global__ void finalize_loss(float* __restrict__ out, int loss_off) {
    out[loss_off] = g_loss * (1.0f / (float)((size_t)BATCH * HWN * CDIM));
}

// ---------------------------------------------------------------------------
extern "C" void kernel_launch(void* const* d_in, const int* in_sizes, int n_in,
                              void* d_out, int out_size) {
    const float* x  = (const float*)d_in[0];   // [16, 256, 64, 64]
    const float* cb = (const float*)d_in[1];   // [1024, 256]
    float* out = (float*)d_out;

    cudaFuncSetAttribute(gemm_mma, cudaFuncAttributeMaxDynamicSharedMemorySize,
                         SMEM_GEMM);

    prep_transpose<<<dim3(KCODES / 32, CDIM / 32), 256>>>(cb);
    prep_c2<<<KCODES, 32>>>(cb);
    split_cb<<<KCODES * CDIM / 256, 256>>>(cb);
    gemm_mma<<<NPIX / 64, 256, SMEM_GEMM>>>(x);
    fixup<<<NPIX / 16, 256>>>(x);
    gather_loss<<<BATCH * HWN / 64, 256>>>(x, cb, out);
    finalize_loss<<<1, 1>>>(out, out_size - 1);
}

// round 16
// speedup vs baseline: 1.6588x; 1.0861x over previous
#include <cuda_runtime.h>
#include <cuda_bf16.h>
#include <cstdint>

#define HWN    4096
#define CDIM   256
#define KCODES 1024
#define BATCH  16
#define NPIX   (BATCH * HWN)
#define MARGIN 0.012f

// ---------------------------------------------------------------------------
// Device-global scratch
// ---------------------------------------------------------------------------
__device__ __align__(16) __nv_bfloat16 g_cbh[KCODES * CDIM];
__device__ __align__(16) __nv_bfloat16 g_cbl[KCODES * CDIM];
__device__ float g_ct[CDIM * KCODES];   // codebook transposed (exact fixup)
__device__ float g_c2[KCODES];
__device__ int   g_inds[NPIX];
__device__ int   g_flag[NPIX];
__device__ int   g_nflag;
__device__ float g_loss;

// ---------------------------------------------------------------------------
__device__ __forceinline__ void split2(float v, uint16_t& h, uint16_t& l) {
    __nv_bfloat16 bh = __float2bfloat16_rn(v);
    __nv_bfloat16 bl = __float2bfloat16_rn(v - __bfloat162float(bh));
    h = __bfloat16_as_ushort(bh);
    l = __bfloat16_as_ushort(bl);
}

__device__ __forceinline__ uint32_t smem_u32(const void* p) {
    uint32_t a;
    asm("{ .reg .u64 t; cvta.to.shared.u64 t, %1; cvt.u32.u64 %0, t; }" : "=r"(a) : "l"(p));
    return a;
}
__device__ __forceinline__ void cp16(uint32_t dst, const void* src) {
    asm volatile("cp.async.cg.shared.global [%0], [%1], 16;" :: "r"(dst), "l"(src) : "memory");
}
#define CP_COMMIT() asm volatile("cp.async.commit_group;" ::: "memory")
#define CP_WAIT1()  asm volatile("cp.async.wait_group 1;" ::: "memory")
#define CP_WAIT0()  asm volatile("cp.async.wait_group 0;" ::: "memory")

__device__ __forceinline__ void ldsm4(uint32_t* r, uint32_t addr) {
    asm volatile("ldmatrix.sync.aligned.m8n8.x4.shared.b16 {%0,%1,%2,%3}, [%4];"
                 : "=r"(r[0]), "=r"(r[1]), "=r"(r[2]), "=r"(r[3]) : "r"(addr));
}
__device__ __forceinline__ void mma16816(float* d, const uint32_t* a,
                                         const uint32_t* b) {
    asm volatile(
        "mma.sync.aligned.m16n8k16.row.col.f32.bf16.bf16.f32 "
        "{%0,%1,%2,%3}, {%4,%5,%6,%7}, {%8,%9}, {%0,%1,%2,%3};"
        : "+f"(d[0]), "+f"(d[1]), "+f"(d[2]), "+f"(d[3])
        : "r"(a[0]), "r"(a[1]), "r"(a[2]), "r"(a[3]), "r"(b[0]), "r"(b[1]));
}

// ---------------------------------------------------------------------------
// Prep kernels
// ---------------------------------------------------------------------------
__global__ void prep_transpose(const float* __restrict__ cb) {
    __shared__ float tile[32][33];
    int k0 = blockIdx.x * 32, c0 = blockIdx.y * 32;
    int tx = threadIdx.x & 31, r0 = threadIdx.x >> 5;
#pragma unroll
    for (int i = 0; i < 4; i++)
        tile[r0 + i * 8][tx] = cb[(size_t)(k0 + r0 + i * 8) * CDIM + c0 + tx];
    __syncthreads();
#pragma unroll
    for (int i = 0; i < 4; i++)
        g_ct[(size_t)(c0 + r0 + i * 8) * KCODES + k0 + tx] = tile[tx][r0 + i * 8];
    if (blockIdx.x == 0 && blockIdx.y == 0 && threadIdx.x == 0) {
        g_loss = 0.0f;
        g_nflag = 0;
    }
}

__global__ void prep_c2(const float* __restrict__ cb) {
    int k = blockIdx.x, lane = threadIdx.x;
    float s = 0.0f;
#pragma unroll
    for (int c = lane; c < CDIM; c += 32) {
        float v = cb[(size_t)k * CDIM + c];
        s += v * v;
    }
#pragma unroll
    for (int o = 16; o; o >>= 1) s += __shfl_xor_sync(0xffffffffu, s, o);
    if (lane == 0) g_c2[k] = s;
}

__global__ __launch_bounds__(256) void split_cb(const float* __restrict__ cb) {
    int i = blockIdx.x * 256 + threadIdx.x;
    float v = cb[i];
    uint16_t h, l;
    split2(v, h, l);
    g_cbh[i] = __ushort_as_bfloat16(h);
    g_cbl[i] = __ushort_as_bfloat16(l);
}

// ---------------------------------------------------------------------------
// Tensor-core approximate GEMM + top-2 argmin + flagging.
// CTA: 64 pixels x 1024 codes, 16 warps (4/SMSP), warp tile 32px x 16 codes.
// A split fused in-prologue from fp32 x. B chunks (128 codes x 64 ch x 2
// splits) 3-stage cp.async pipeline, single sync per chunk.
// ---------------------------------------------------------------------------
#define APITCH 528
#define BPITCH 144
#define OFF_AH 0
#define OFF_AL 33792
#define OFF_B  67584
#define BUFSZ  36864
#define SPLSZ  18432
#define OFF_C2 178176
#define OFF_RB 182272
#define OFF_RS 184320
#define OFF_RI 186368
#define SMEM_GEMM 188416

__global__ __launch_bounds__(512, 1) void gemm_mma(const float* __restrict__ x) {
    extern __shared__ __align__(16) unsigned char smem[];
    const uint32_t smb = smem_u32(smem);
    const int tid = threadIdx.x;
    const int wid = tid >> 5, lane = tid & 31;
    const int g = lane >> 2, tig = lane & 3;
    const int warpM = wid & 1;                // 32 px per M-half
    const int warpN = wid >> 1;               // 8 N-groups, 16 codes each
    const int laneR = lane & 15, laneK = (lane >> 4) << 3;

    auto issueB = [&](int ch, int buf) {
        const int nt = ch >> 2, kc = ch & 3;
        const uint32_t dbase = smb + OFF_B + buf * BUFSZ;
#pragma unroll
        for (int s = 0; s < 2; s++) {
            const uint4* src = (const uint4*)(s ? g_cbl : g_cbh);
            uint32_t db = dbase + s * SPLSZ;
#pragma unroll
            for (int i = 0; i < 2; i++) {
                int idx = tid + i * 512;
                int r = idx >> 3, q = idx & 7;
                cp16(db + r * BPITCH + q * 16, src + (nt * 128 + r) * 32 + kc * 8 + q);
            }
        }
        CP_COMMIT();
    };

    // ---- pipeline prologue: chunks 0,1 in flight ----
    issueB(0, 0);
    issueB(1, 1);

    // ---- fused A load + split (overlaps with cp.async) ----
    {
        const int b = blockIdx.x >> 6;
        const int n0 = (blockIdx.x & 63) * 64;
        const int px = tid & 63, cg8 = tid >> 6;   // 8 channel groups of 32
        const float* xb = x + (size_t)b * CDIM * HWN + n0 + px;
        unsigned char* ahb = smem + OFF_AH + px * APITCH;
        unsigned char* alb = smem + OFF_AL + px * APITCH;
#pragma unroll 8
        for (int i = 0; i < 32; i++) {
            int c = cg8 * 32 + i;
            float v = __ldg(xb + (size_t)c * HWN);
            uint16_t h, l;
            split2(v, h, l);
            *(uint16_t*)(ahb + c * 2) = h;
            *(uint16_t*)(alb + c * 2) = l;
        }
#pragma unroll
        for (int i = 0; i < 2; i++)
            ((float*)(smem + OFF_C2))[tid + i * 512] = g_c2[tid + i * 512];
    }

    float bestv[4], secv[4];
    int bidx[4];
#pragma unroll
    for (int r = 0; r < 4; r++) { bestv[r] = 3.4e38f; secv[r] = 3.4e38f; bidx[r] = 0; }
    const float* c2s = (const float*)(smem + OFF_C2);

    float acc[2][2][4];
    const uint32_t aAddrH = smb + OFF_AH + (warpM * 32 + laneR) * APITCH + laneK * 2;
    const uint32_t aAddrL = smb + OFF_AL + (warpM * 32 + laneR) * APITCH + laneK * 2;
    const uint32_t bAddr  = smb + OFF_B + (warpN * 16 + laneR) * BPITCH + laneK * 2;

#pragma unroll 1
    for (int ci = 0; ci < 32; ci++) {
        const int nt = ci >> 2, kc = ci & 3, buf = ci % 3;
        if (ci == 31) { CP_WAIT0(); } else { CP_WAIT1(); }
        __syncthreads();   // publishes chunk ci; guards buf (ci+2)%3 reuse

        if (kc == 0) {
#pragma unroll
            for (int mi = 0; mi < 2; mi++)
#pragma unroll
                for (int ni = 0; ni < 2; ni++)
#pragma unroll
                    for (int e = 0; e < 4; e++) acc[mi][ni][e] = 0.0f;
        }

        const uint32_t bH = bAddr + buf * BUFSZ;
        const uint32_t bL = bH + SPLSZ;
#pragma unroll
        for (int ks = 0; ks < 4; ks++) {
            const uint32_t ak = (uint32_t)(kc * 64 + ks * 16) * 2;
            uint32_t ah[2][4], al[2][4];
#pragma unroll
            for (int mi = 0; mi < 2; mi++) {
                ldsm4(ah[mi], aAddrH + mi * (16 * APITCH) + ak);
                ldsm4(al[mi], aAddrL + mi * (16 * APITCH) + ak);
            }
            uint32_t bh[2][2], bl[2][2], r4[4];
            ldsm4(r4, bH + ks * 32);
            bh[0][0] = r4[0]; bh[1][0] = r4[1]; bh[0][1] = r4[2]; bh[1][1] = r4[3];
            ldsm4(r4, bL + ks * 32);
            bl[0][0] = r4[0]; bl[1][0] = r4[1]; bl[0][1] = r4[2]; bl[1][1] = r4[3];

#pragma unroll
            for (int mi = 0; mi < 2; mi++)
#pragma unroll
                for (int ni = 0; ni < 2; ni++)
                    mma16816(acc[mi][ni], ah[mi], bh[ni]);
#pragma unroll
            for (int mi = 0; mi < 2; mi++)
#pragma unroll
                for (int ni = 0; ni < 2; ni++)
                    mma16816(acc[mi][ni], ah[mi], bl[ni]);
#pragma unroll
            for (int mi = 0; mi < 2; mi++)
#pragma unroll
                for (int ni = 0; ni < 2; ni++)
                    mma16816(acc[mi][ni], al[mi], bh[ni]);
        }

        if (kc == 3) {
            // fold into per-lane top-2 (ascending code order per row slot)
#pragma unroll
            for (int ni = 0; ni < 2; ni++) {
                int cg = nt * 128 + warpN * 16 + ni * 8 + tig * 2;
                float c20 = c2s[cg], c21 = c2s[cg + 1];
#pragma unroll
                for (int mi = 0; mi < 2; mi++) {
#pragma unroll
                    for (int e = 0; e < 4; e++) {
                        int r4s = mi * 2 + (e >> 1);
                        float v = fmaf(-2.0f, acc[mi][ni][e], (e & 1) ? c21 : c20);
                        int k = cg + (e & 1);
                        if (v < bestv[r4s]) {
                            secv[r4s] = bestv[r4s];
                            bestv[r4s] = v;
                            bidx[r4s] = k;
                        } else if (v < secv[r4s]) {
                            secv[r4s] = v;
                        }
                    }
                }
            }
        }

        if (ci < 30) issueB(ci + 2, (ci + 2) % 3);
    }

    // ---- quad merge (lanes with same g share rows) ----
#pragma unroll
    for (int o = 1; o <= 2; o <<= 1) {
#pragma unroll
        for (int r = 0; r < 4; r++) {
            float ob = __shfl_xor_sync(0xffffffffu, bestv[r], o);
            float os = __shfl_xor_sync(0xffffffffu, secv[r], o);
            int oi = __shfl_xor_sync(0xffffffffu, bidx[r], o);
            bool take = (ob < bestv[r]) || (ob == bestv[r] && oi < bidx[r]);
            float loser = take ? bestv[r] : ob;
            if (take) { bestv[r] = ob; bidx[r] = oi; }
            secv[r] = fminf(fminf(secv[r], os), loser);
        }
    }

    float* redb = (float*)(smem + OFF_RB);
    float* reds = (float*)(smem + OFF_RS);
    int*   redi = (int*)(smem + OFF_RI);
    if (tig == 0) {
#pragma unroll
        for (int r4s = 0; r4s < 4; r4s++) {
            int row = warpM * 32 + (r4s >> 1) * 16 + (r4s & 1) * 8 + g;  // 0..63
            redb[warpN * 64 + row] = bestv[r4s];
            reds[warpN * 64 + row] = secv[r4s];
            redi[warpN * 64 + row] = bidx[r4s];
        }
    }
    __syncthreads();

    if (tid < 64) {
        float bv = 3.4e38f, sv = 3.4e38f;
        int bi = 0x7fffffff;
#pragma unroll
        for (int w = 0; w < 8; w++) {
            float ob = redb[w * 64 + tid];
            float os = reds[w * 64 + tid];
            int oi = redi[w * 64 + tid];
            bool take = (ob < bv) || (ob == bv && oi < bi);
            float loser = take ? bv : ob;
            if (take) { bv = ob; bi = oi; }
            sv = fminf(fminf(sv, os), loser);
        }
        int pixel = blockIdx.x * 64 + tid;
        g_inds[pixel] = bi;
        if (sv - bv < MARGIN) {
            int slot = atomicAdd(&g_nflag, 1);
            g_flag[slot] = pixel;
        }
    }
}

// ---------------------------------------------------------------------------
// Exact fp32 fixup: 16 flagged pixels per block x all 1024 codes.
// ---------------------------------------------------------------------------
__global__ __launch_bounds__(256) void fixup(const float* __restrict__ x) {
    int nflag = g_nflag;
    int base = blockIdx.x * 16;
    if (base >= nflag) return;

    __shared__ float As[32][17];
    __shared__ float Bs[32][64];
    __shared__ float rv[16][17];
    __shared__ int   ri[16][17];
    __shared__ int   pid[16];
    __shared__ size_t pbase[16];

    const int tid = threadIdx.x;
    if (tid < 16) {
        int src = base + tid;
        if (src >= nflag) src = base;
        int p = g_flag[src];
        pid[tid] = p;
        pbase[tid] = (size_t)(p >> 12) * CDIM * HWN + (p & 4095);
    }
    __syncthreads();

    const int tx = tid & 15, ty = tid >> 4;
    float best = 3.4e38f;
    int besti = 0;

    for (int kt = 0; kt < 16; kt++) {
        float acc[4] = {0.0f, 0.0f, 0.0f, 0.0f};
#pragma unroll 1
        for (int cc = 0; cc < CDIM; cc += 32) {
#pragma unroll
            for (int i = 0; i < 2; i++) {
                int idx = tid + i * 256;
                int r = idx >> 4, px = idx & 15;
                As[r][px] = x[pbase[px] + (size_t)(cc + r) * HWN];
            }
#pragma unroll
            for (int i = 0; i < 8; i++) {
                int idx = tid + i * 256;
                int r = idx >> 6, col = idx & 63;
                Bs[r][col] = g_ct[(size_t)(cc + r) * KCODES + kt * 64 + col];
            }
            __syncthreads();
#pragma unroll
            for (int c = 0; c < 32; c++) {
                float a = As[c][ty];
                float4 b4 = *(const float4*)&Bs[c][tx * 4];
                acc[0] = fmaf(a, b4.x, acc[0]);
                acc[1] = fmaf(a, b4.y, acc[1]);
                acc[2] = fmaf(a, b4.z, acc[2]);
                acc[3] = fmaf(a, b4.w, acc[3]);
            }
            __syncthreads();
        }
#pragma unroll
        for (int j = 0; j < 4; j++) {
            int k = kt * 64 + tx * 4 + j;
            float d = fmaf(-2.0f, acc[j], g_c2[k]);
            if (d < best) { best = d; besti = k; }
        }
    }

    rv[ty][tx] = best;
    ri[ty][tx] = besti;
    __syncthreads();
    if (tid < 16) {
        float bv = 3.4e38f;
        int bi = 0x7fffffff;
#pragma unroll
        for (int t = 0; t < 16; t++) {
            float v = rv[tid][t];
            int id = ri[tid][t];
            if (v < bv || (v == bv && id < bi)) { bv = v; bi = id; }
        }
        g_inds[pid[tid]] = bi;   // duplicate pixels write identical values
    }
}

// ---------------------------------------------------------------------------
// Gather + loss
// ---------------------------------------------------------------------------
__global__ __launch_bounds__(256) void gather_loss(const float* __restrict__ x,
                                                   const float* __restrict__ cb,
                                                   float* __restrict__ out) {
    int t = blockIdx.x;
    int b  = t >> 6;
    int n0 = (t & 63) * 64;
    int nl = threadIdx.x & 63;
    int c0 = (threadIdx.x >> 6) * 64;

    int idx = g_inds[b * HWN + n0 + nl];
    const float4* crow = (const float4*)(cb + (size_t)idx * CDIM + c0);
    const float* xb = x   + ((size_t)b * CDIM + c0) * HWN + n0 + nl;
    float*       ob = out + ((size_t)b * CDIM + c0) * HWN + n0 + nl;

    float lsum = 0.0f;
#pragma unroll 4
    for (int i = 0; i < 16; i++) {
        float4 q = __ldg(crow + i);
        float qv[4] = {q.x, q.y, q.z, q.w};
#pragma unroll
        for (int u = 0; u < 4; u++) {
            size_t off = (size_t)(i * 4 + u) * HWN;
            float xv = xb[off];
            ob[off] = qv[u];
            float d = qv[u] - xv;
            lsum = fmaf(d, d, lsum);
        }
    }
#pragma unroll
    for (int o = 16; o; o >>= 1) lsum += __shfl_xor_sync(0xffffffffu, lsum, o);
    __shared__ float ws[8];
    if ((threadIdx.x & 31) == 0) ws[threadIdx.x >> 5] = lsum;
    __syncthreads();
    if (threadIdx.x == 0) {
        float s = 0.0f;
#pragma unroll
        for (int w = 0; w < 8; w++) s += ws[w];
        atomicAdd(&g_loss, s);
    }
}

__global__ void finalize_loss(float* __restrict__ out, int loss_off) {
    out[loss_off] = g_loss * (1.0f / (float)((size_t)BATCH * HWN * CDIM));
}

// ---------------------------------------------------------------------------
extern "C" void kernel_launch(void* const* d_in, const int* in_sizes, int n_in,
                              void* d_out, int out_size) {
    const float* x  = (const float*)d_in[0];   // [16, 256, 64, 64]
    const float* cb = (const float*)d_in[1];   // [1024, 256]
    float* out = (float*)d_out;

    cudaFuncSetAttribute(gemm_mma, cudaFuncAttributeMaxDynamicSharedMemorySize,
                         SMEM_GEMM);

    prep_transpose<<<dim3(KCODES / 32, CDIM / 32), 256>>>(cb);
    prep_c2<<<KCODES, 32>>>(cb);
    split_cb<<<KCODES * CDIM / 256, 256>>>(cb);
    gemm_mma<<<NPIX / 64, 512, SMEM_GEMM>>>(x);
    fixup<<<NPIX / 16, 256>>>(x);
    gather_loss<<<BATCH * HWN / 64, 256>>>(x, cb, out);
    finalize_loss<<<1, 1>>>(out, out_size - 1);
}